// round 13
// baseline (speedup 1.0000x reference)
#include <cuda_runtime.h>
#include <cuda_bf16.h>

#define BSZ 512
#define LSEQ 60
#define DIM 300
#define HID 256
#define G4 1024
#define ROWS_A 8

typedef unsigned long long ull;

// run map: 0=lstm1(x1,s1) 1=lstm2(x2,s2) 2=lstm1(x2,s2) 3=lstm2(x1,s1)
__device__ float g_XG[4][(size_t)BSZ * LSEQ * G4];
__device__ float g_Ybuf[4][(size_t)BSZ * LSEQ * HID];
__device__ float g_h[2][4][BSZ * HID];
__device__ float g_c[4][BSZ * HID];
__device__ float g_WyY[2][(size_t)BSZ * LSEQ * HID];
__device__ float g_WhY2[2][(size_t)BSZ * LSEQ * HID];
__device__ float g_rsel[2][BSZ * HID];
__device__ unsigned g_barL;

__device__ __forceinline__ float tanh_(float x) {
    x = fminf(15.0f, fmaxf(-15.0f, x));
    float e = __expf(2.0f * x);
    return __fdividef(e - 1.0f, e + 1.0f);
}
__device__ __forceinline__ float sigm_(float x) {
    x = fminf(30.0f, fmaxf(-30.0f, x));
    return __fdividef(1.0f, 1.0f + __expf(-x));
}
__device__ __forceinline__ float tanha(float x) {   // HW tanh MUFU op
    float y; asm("tanh.approx.f32 %0, %1;" : "=f"(y) : "f"(x)); return y;
}

// ---- packed f32x2 helpers ----
__device__ __forceinline__ ull pk2(float x, float y) {
    ull r; asm("mov.b64 %0, {%1, %2};" : "=l"(r) : "f"(x), "f"(y)); return r;
}
__device__ __forceinline__ void fma2(ull& d, ull a, ull b) {
    asm("fma.rn.f32x2 %0, %1, %2, %0;" : "+l"(d) : "l"(a), "l"(b));
}
__device__ __forceinline__ void upk2(ull v, float& lo, float& hi) {
    asm("mov.b64 {%0, %1}, %2;" : "=f"(lo), "=f"(hi) : "l"(v));
}

// ---- cp.async helpers ----
__device__ __forceinline__ void cpa16(void* dst, const void* src, int bytes) {
    unsigned d = (unsigned)__cvta_generic_to_shared(dst);
    asm volatile("cp.async.cg.shared.global [%0], [%1], 16, %2;" :: "r"(d), "l"(src), "r"(bytes));
}
__device__ __forceinline__ void cpa_commit() { asm volatile("cp.async.commit_group;"); }
__device__ __forceinline__ void cpa_wait1() { asm volatile("cp.async.wait_group 1;"); }
__device__ __forceinline__ void cpa_wait0() { asm volatile("cp.async.wait_group 0;"); }

// ---- software grid barrier (all CTAs resident by construction) ----
__device__ __forceinline__ void grid_barrier(unsigned target) {
    __syncthreads();
    if (threadIdx.x == 0) {
        __threadfence();
        atomicAdd(&g_barL, 1u);
        while (*(volatile unsigned*)&g_barL < target) {}
        __threadfence();
    }
    __syncthreads();
}

__global__ void init_kernel() {
    int idx = blockIdx.x * blockDim.x + threadIdx.x;
    int stride = gridDim.x * blockDim.x;
    const int n = BSZ * HID;
    float* ph = &g_h[0][0][0];
    float* pc = &g_c[0][0];
    float* ps = &g_rsel[0][0];
    for (int i = idx; i < 8 * n; i += stride) ph[i] = 0.0f;
    for (int i = idx; i < 4 * n; i += stride) pc[i] = 0.0f;
    for (int i = idx; i < 2 * n; i += stride) ps[i] = 0.0f;
    if (idx == 0) g_barL = 0u;
}

// ---------- gather + input projection: XG[run] = E[tok] @ Wx + b ----------
__global__ __launch_bounds__(256) void xg_gemm(
    const float* __restrict__ E,
    const float* __restrict__ Wx1, const float* __restrict__ b1,
    const float* __restrict__ Wx2, const float* __restrict__ b2,
    const int* __restrict__ in1, const int* __restrict__ in2)
{
    const int src = blockIdx.z;
    const int* tok = src == 0 ? in1 : in2;
    const int m0 = blockIdx.x * 128;
    const int n0g = blockIdx.y * 256;
    const bool isW2 = n0g >= G4;
    const float* W = isW2 ? Wx2 : Wx1;
    const float* bias = isW2 ? b2 : b1;
    const int n0 = isW2 ? (n0g - G4) : n0g;
    const int run = isW2 ? (src == 0 ? 3 : 1) : (src == 0 ? 0 : 2);
    float* C = g_XG[run];

    __shared__ float As[2][128][12];
    __shared__ float Bs[2][8][256];

    const int tid = threadIdx.x;
    const int rthr = tid >> 4;
    const int cthr = tid & 15;

    const int arow = tid >> 1;
    const int akq = (tid & 1) * 4;
    const long aBase = (long)tok[m0 + arow] * DIM;

    const int NB = (DIM + 7) / 8;  // 38

    ull acc2[8][8];
#pragma unroll
    for (int i = 0; i < 8; i++)
#pragma unroll
        for (int j = 0; j < 8; j++) acc2[i][j] = 0ull;

    auto loadAB = [&](int buf, int kb) {
        int kA = kb * 8 + akq;
        int remA = DIM - kA;
        int bytesA = remA >= 4 ? 16 : (remA > 0 ? remA * 4 : 0);
        cpa16(&As[buf][arow][akq], &E[aBase + (kA < DIM ? kA : 0)], bytesA);
#pragma unroll
        for (int p = 0; p < 2; p++) {
            int i = p * 256 + tid;
            int kk = i >> 6;
            int c4 = (i & 63) * 4;
            int k = kb * 8 + kk;
            int bytesB = (k < DIM) ? 16 : 0;
            cpa16(&Bs[buf][kk][c4], &W[(long)(k < DIM ? k : 0) * G4 + n0 + c4], bytesB);
        }
    };

    loadAB(0, 0);
    cpa_commit();

    for (int kb = 0; kb < NB; kb++) {
        int buf = kb & 1;
        if (kb + 1 < NB) { loadAB(buf ^ 1, kb + 1); cpa_commit(); cpa_wait1(); }
        else cpa_wait0();
        __syncthreads();
#pragma unroll
        for (int kk = 0; kk < 8; kk++) {
            ull a2[8];
#pragma unroll
            for (int i = 0; i < 8; i++) {
                float a = As[buf][rthr * 8 + i][kk];
                a2[i] = pk2(a, a);
            }
            ull b2v[8];
#pragma unroll
            for (int j = 0; j < 8; j++)
                b2v[j] = *reinterpret_cast<const ull*>(&Bs[buf][kk][2 * cthr + 32 * j]);
#pragma unroll
            for (int i = 0; i < 8; i++)
#pragma unroll
                for (int j = 0; j < 8; j++) fma2(acc2[i][j], a2[i], b2v[j]);
        }
        __syncthreads();
    }

#pragma unroll
    for (int i = 0; i < 8; i++) {
        const long rowOff = (long)(m0 + rthr * 8 + i) * G4 + n0;
#pragma unroll
        for (int j = 0; j < 8; j++) {
            int col = 2 * cthr + 32 * j;
            float lo, hi; upk2(acc2[i][j], lo, hi);
            float2 v = make_float2(lo + bias[n0 + col], hi + bias[n0 + col + 1]);
            *reinterpret_cast<float2*>(&C[rowOff + col]) = v;
        }
    }
}

// ---------- batched [30720,256]x[256,128] products, register-prefetch pipelined ----------
// z=0: WyY[0]=Y(run0)@W_y  z=1: WyY[1]=Y(run2)@W_y
// z=2: WhY2[0]=Y(run1)@Wh_a  z=3: WhY2[1]=Y(run3)@Wh_a
__global__ __launch_bounds__(256, 2) void bgemm(
    const float* __restrict__ W_y, const float* __restrict__ Wh_a)
{
    const int z = blockIdx.z;
    const float* A = g_Ybuf[z == 0 ? 0 : z == 1 ? 2 : z == 2 ? 1 : 3];
    const float* B = (z < 2) ? W_y : Wh_a;
    float* C = (z < 2) ? g_WyY[z] : g_WhY2[z - 2];
    const int m0 = blockIdx.x * 128;
    const int n0 = blockIdx.y * 128;

    __shared__ float As[8][128];
    __shared__ float Bs[8][128];

    const int tid = threadIdx.x;
    const int tm = (tid >> 4) * 8;
    const int tn = (tid & 15) * 8;
    const int lm = tid >> 1;
    const int kq = (tid & 1) * 4;
    const int bkk = tid >> 5;
    const int bn4 = (tid & 31) * 4;

    ull acc2[8][4];
#pragma unroll
    for (int i = 0; i < 8; i++)
#pragma unroll
        for (int j = 0; j < 4; j++) acc2[i][j] = 0ull;

    // prefetch first k-block into registers
    float4 av = *reinterpret_cast<const float4*>(&A[(long)(m0 + lm) * HID + kq]);
    float4 bv = *reinterpret_cast<const float4*>(&B[(long)bkk * HID + n0 + bn4]);

    for (int k0 = 0; k0 < HID; k0 += 8) {
        As[kq + 0][lm] = av.x; As[kq + 1][lm] = av.y;
        As[kq + 2][lm] = av.z; As[kq + 3][lm] = av.w;
        *reinterpret_cast<float4*>(&Bs[bkk][bn4]) = bv;
        __syncthreads();
        if (k0 + 8 < HID) {   // prefetch next block while computing this one
            av = *reinterpret_cast<const float4*>(&A[(long)(m0 + lm) * HID + k0 + 8 + kq]);
            bv = *reinterpret_cast<const float4*>(&B[(long)(k0 + 8 + bkk) * HID + n0 + bn4]);
        }
#pragma unroll
        for (int kk = 0; kk < 8; kk++) {
            float4 t0 = *reinterpret_cast<const float4*>(&As[kk][tm]);
            float4 t1 = *reinterpret_cast<const float4*>(&As[kk][tm + 4]);
            ull a2[8];
            a2[0] = pk2(t0.x, t0.x); a2[1] = pk2(t0.y, t0.y);
            a2[2] = pk2(t0.z, t0.z); a2[3] = pk2(t0.w, t0.w);
            a2[4] = pk2(t1.x, t1.x); a2[5] = pk2(t1.y, t1.y);
            a2[6] = pk2(t1.z, t1.z); a2[7] = pk2(t1.w, t1.w);
            const ull* bp = reinterpret_cast<const ull*>(&Bs[kk][tn]);
            ull b2v[4] = {bp[0], bp[1], bp[2], bp[3]};
#pragma unroll
            for (int i = 0; i < 8; i++)
#pragma unroll
                for (int j = 0; j < 4; j++) fma2(acc2[i][j], a2[i], b2v[j]);
        }
        __syncthreads();
    }
#pragma unroll
    for (int i = 0; i < 8; i++) {
        float* Cp = &C[(long)(m0 + tm + i) * HID + n0 + tn];
#pragma unroll
        for (int j = 0; j < 4; j++) {
            float lo, hi; upk2(acc2[i][j], lo, hi);
            Cp[2 * j] = lo;
            Cp[2 * j + 1] = hi;
        }
    }
}

// ---------- persistent LSTM: all 60 steps in one launch ----------
__global__ __launch_bounds__(512) void lstm_persist(
    const float* __restrict__ Wh1, const float* __restrict__ Wh2,
    const int* __restrict__ s1, const int* __restrict__ s2)
{
    const int run = blockIdx.z;
    const float* Wh = (run == 0 || run == 2) ? Wh1 : Wh2;
    const int* slen = (run == 0 || run == 3) ? s1 : s2;
    const int b0 = blockIdx.x * 64;
    const int h0 = blockIdx.y * 64;
    float* cst = g_c[run];
    float* Y = g_Ybuf[run];
    const float* XG = g_XG[run];

    const int tid = threadIdx.x;
    const int hl = tid & 31;
    const int rg = tid >> 5;   // 0..15 -> rows rg*4..+3

    __shared__ int sh_sl[64];
    __shared__ float As[2][64][20];
    __shared__ float Bs[2][16][256];

    if (tid < 64) sh_sl[tid] = slen[b0 + tid];
    __syncthreads();

    for (int t = 0; t < LSEQ; t++) {
        const float* hin = g_h[t & 1][run];
        float* hout = g_h[(t + 1) & 1][run];

        int anyAct = __syncthreads_or((tid < 64) ? (t < sh_sl[tid]) : 0);
        if (!anyAct) {
#pragma unroll
            for (int p = 0; p < 4; p++) {
                int idx = p * 512 + tid;
                int row = idx >> 5;
                int h = h0 + (idx & 31) * 2;
                int b = b0 + row;
                *reinterpret_cast<float2*>(&hout[b * HID + h]) =
                    *reinterpret_cast<const float2*>(&hin[b * HID + h]);
                *reinterpret_cast<float2*>(&Y[((long)b * LSEQ + t) * HID + h]) =
                    make_float2(0.0f, 0.0f);
            }
            grid_barrier(128u * (unsigned)(t + 1));
            continue;
        }

        auto loadAB = [&](int buf, int kb) {
            int k0 = kb * 16;
            if (tid < 256)
                cpa16(&As[buf][tid >> 2][(tid & 3) * 4],
                      &hin[(b0 + (tid >> 2)) * HID + k0 + (tid & 3) * 4], 16);
#pragma unroll
            for (int p = 0; p < 2; p++) {
                int i = p * 512 + tid;
                int kk = i >> 6;
                int cw = (i & 63) * 4;
                int g = cw >> 6;
                int wn = cw & 63;
                cpa16(&Bs[buf][kk][cw], &Wh[(long)(k0 + kk) * G4 + g * HID + h0 + wn], 16);
            }
        };

        ull acc2[4][4];
#pragma unroll
        for (int i = 0; i < 4; i++)
#pragma unroll
            for (int g = 0; g < 4; g++) acc2[i][g] = 0ull;

        const int NB = HID / 16;  // 16
        loadAB(0, 0);
        cpa_commit();

        for (int kb = 0; kb < NB; kb++) {
            int buf = kb & 1;
            if (kb + 1 < NB) { loadAB(buf ^ 1, kb + 1); cpa_commit(); cpa_wait1(); }
            else cpa_wait0();
            __syncthreads();
#pragma unroll
            for (int kk = 0; kk < 16; kk++) {
                ull a2[4];
#pragma unroll
                for (int rr = 0; rr < 4; rr++) {
                    float a = As[buf][rg * 4 + rr][kk];
                    a2[rr] = pk2(a, a);
                }
                ull b2v[4];
#pragma unroll
                for (int g = 0; g < 4; g++)
                    b2v[g] = *reinterpret_cast<const ull*>(&Bs[buf][kk][g * 64 + hl * 2]);
#pragma unroll
                for (int rr = 0; rr < 4; rr++)
#pragma unroll
                    for (int g = 0; g < 4; g++) fma2(acc2[rr][g], a2[rr], b2v[g]);
            }
            __syncthreads();
        }

        const int h = h0 + hl * 2;
#pragma unroll
        for (int rr = 0; rr < 4; rr++) {
            const int b = b0 + rg * 4 + rr;
            const bool act = t < sh_sl[rg * 4 + rr];
            const float* xg = &XG[((long)b * LSEQ + t) * G4 + h];
            float ix, iy, jx, jy, fx, fy, ox, oy;
            upk2(acc2[rr][0], ix, iy);
            upk2(acc2[rr][1], jx, jy);
            upk2(acc2[rr][2], fx, fy);
            upk2(acc2[rr][3], ox, oy);
            float2 xi = *reinterpret_cast<const float2*>(&xg[0]);
            float2 xj = *reinterpret_cast<const float2*>(&xg[HID]);
            float2 xf = *reinterpret_cast<const float2*>(&xg[2 * HID]);
            float2 xo = *reinterpret_cast<const float2*>(&xg[3 * HID]);
            ix += xi.x; iy += xi.y; jx += xj.x; jy += xj.y;
            fx += xf.x; fy += xf.y; ox += xo.x; oy += xo.y;
            float2 cold = *reinterpret_cast<const float2*>(&cst[b * HID + h]);
            float cnx = cold.x * sigm_(fx + 1.0f) + sigm_(ix) * tanh_(jx);
            float cny = cold.y * sigm_(fy + 1.0f) + sigm_(iy) * tanh_(jy);
            float hnx = tanh_(cnx) * sigm_(ox);
            float hny = tanh_(cny) * sigm_(oy);
            float2 hov, yov;
            if (act) {
                *reinterpret_cast<float2*>(&cst[b * HID + h]) = make_float2(cnx, cny);
                hov = make_float2(hnx, hny);
                yov = hov;
            } else {
                hov = *reinterpret_cast<const float2*>(&hin[b * HID + h]);
                yov = make_float2(0.0f, 0.0f);
            }
            *reinterpret_cast<float2*>(&hout[b * HID + h]) = hov;
            *reinterpret_cast<float2*>(&Y[((long)b * LSEQ + t) * HID + h]) = yov;
        }

        grid_barrier(128u * (unsigned)(t + 1));
    }
}

// ---------- persistent attention: each CTA scans its 8 rows privately ----------
// r state stored transposed (sh_rT[k][row]) so the tmp-GEMM packs row-pairs into FMA2.
__global__ __launch_bounds__(256) void attn_persist(
    const float* __restrict__ Wr_a, const float* __restrict__ Wt_a,
    const float* __restrict__ w_a,
    const int* __restrict__ s1, const int* __restrict__ s2)
{
    const int br = blockIdx.y;
    const int b0 = blockIdx.x * ROWS_A;
    const float* Y  = g_Ybuf[br == 0 ? 0 : 2];
    const float* WyY = g_WyY[br];
    const float* WhY2 = g_WhY2[br];
    const int* msel  = br == 0 ? s2 : s1;
    const int* mmask = br == 0 ? s1 : s2;
    float* rsel = g_rsel[br];

    const int tid = threadIdx.x;
    const int lane = tid & 31;
    const int w = tid >> 5;

    __shared__ float sh_rT[HID][ROWS_A];   // transposed r state
    __shared__ float sh_tmp[ROWS_A][HID];
    __shared__ float sh_rt[ROWS_A][HID];
    __shared__ float sh_sc[ROWS_A][64];
    __shared__ float sh_al[ROWS_A][64];
    __shared__ float sh_wa[HID];
    __shared__ int sh_sel[ROWS_A], sh_ml[ROWS_A], sh_tmax;

    if (tid < ROWS_A) { sh_sel[tid] = msel[b0 + tid]; sh_ml[tid] = mmask[b0 + tid]; }
    sh_wa[tid] = w_a[tid];
#pragma unroll
    for (int rb = 0; rb < ROWS_A; rb++) sh_rT[tid][rb] = 0.0f;
    __syncthreads();
    if (tid == 0) {
        int m = 0;
#pragma unroll
        for (int i = 0; i < ROWS_A; i++) m = max(m, sh_sel[i]);
        sh_tmax = m;
    }
    __syncthreads();
    const int tmax = sh_tmax;

    for (int t = 0; t < tmax; t++) {
        // tmp = WhY2[:,t,:] + r @ Wr_a ; rt = r @ Wt_a   (column tid; row-pairs in FMA2)
        {
            ull accr[4], acct[4];
#pragma unroll
            for (int p = 0; p < 4; p++) { accr[p] = 0ull; acct[p] = 0ull; }
#pragma unroll 4
            for (int k = 0; k < HID; k++) {
                float wr = Wr_a[k * HID + tid];
                float wt = Wt_a[k * HID + tid];
                ull wrr = pk2(wr, wr);
                ull wtt = pk2(wt, wt);
                const ull* rp = reinterpret_cast<const ull*>(&sh_rT[k][0]);
#pragma unroll
                for (int p = 0; p < 4; p++) {
                    ull rv = rp[p];
                    fma2(accr[p], rv, wrr);
                    fma2(acct[p], rv, wtt);
                }
            }
#pragma unroll
            for (int p = 0; p < 4; p++) {
                float a0, a1, t0, t1;
                upk2(accr[p], a0, a1);
                upk2(acct[p], t0, t1);
                sh_tmp[2 * p][tid]     = a0 + WhY2[((long)(b0 + 2 * p) * LSEQ + t) * HID + tid];
                sh_tmp[2 * p + 1][tid] = a1 + WhY2[((long)(b0 + 2 * p + 1) * LSEQ + t) * HID + tid];
                sh_rt[2 * p][tid] = t0;
                sh_rt[2 * p + 1][tid] = t1;
            }
        }
        __syncthreads();

        for (int rb = 0; rb < ROWS_A; rb++) {
            if (t >= sh_sel[rb]) continue;
            const int ml = sh_ml[rb];
            const float* WyYb = &WyY[((long)(b0 + rb) * LSEQ) * HID];
            for (int l = w; l < ml; l += 8) {
                float part = 0.0f;
                const float* row = &WyYb[(long)l * HID];
#pragma unroll
                for (int q = 0; q < 8; q++) {
                    int h = lane + q * 32;
                    part = fmaf(tanha(row[h] + sh_tmp[rb][h]), sh_wa[h], part);
                }
#pragma unroll
                for (int off = 16; off > 0; off >>= 1)
                    part += __shfl_xor_sync(0xFFFFFFFFu, part, off);
                if (lane == 0) sh_sc[rb][l] = part;
            }
        }
        __syncthreads();

        if (w < ROWS_A) {
            int rb = w;
            if (t < sh_sel[rb]) {
                const int ml = sh_ml[rb];
                float v0 = (lane < ml) ? sh_sc[rb][lane] : -1e30f;
                float v1 = (lane + 32 < ml) ? sh_sc[rb][lane + 32] : -1e30f;
                float m = fmaxf(v0, v1);
#pragma unroll
                for (int off = 16; off > 0; off >>= 1)
                    m = fmaxf(m, __shfl_xor_sync(0xFFFFFFFFu, m, off));
                float e0 = (lane < ml) ? __expf(v0 - m) : 0.0f;
                float e1 = (lane + 32 < ml) ? __expf(v1 - m) : 0.0f;
                float s = e0 + e1;
#pragma unroll
                for (int off = 16; off > 0; off >>= 1)
                    s += __shfl_xor_sync(0xFFFFFFFFu, s, off);
                float inv = __fdividef(1.0f, s);
                sh_al[rb][lane] = e0 * inv;
                sh_al[rb][lane + 32] = e1 * inv;
            }
        }
        __syncthreads();

        for (int rb = 0; rb < ROWS_A; rb++) {
            if (t >= sh_sel[rb]) continue;
            const int ml = sh_ml[rb];
            const float* Yb = &Y[((long)(b0 + rb) * LSEQ) * HID];
            float acc = 0.0f;
            for (int l = 0; l < ml; l++)
                acc = fmaf(sh_al[rb][l], Yb[(long)l * HID + tid], acc);
            float rn = acc + tanh_(sh_rt[rb][tid]);
            sh_rT[tid][rb] = rn;
            if (t == sh_sel[rb] - 1) rsel[(b0 + rb) * HID + tid] = rn;
        }
        __syncthreads();
    }
}

// ---------- final combine ----------
__global__ __launch_bounds__(256) void final_combine(
    const float* __restrict__ Wp_a, const float* __restrict__ Wxa,
    const float* __restrict__ U, const float* __restrict__ b_out,
    float* __restrict__ out)
{
    const int b = blockIdx.x;
    const int tid = threadIdx.x;
    __shared__ float sh_a[4][HID];
    __shared__ float red0[256], red1[256];

    sh_a[0][tid] = g_rsel[0][b * HID + tid];
    sh_a[1][tid] = g_h[0][1][b * HID + tid];   // LSEQ even -> final h in buf 0
    sh_a[2][tid] = g_rsel[1][b * HID + tid];
    sh_a[3][tid] = g_h[0][3][b * HID + tid];
    __syncthreads();

    float v = 0.0f;
#pragma unroll
    for (int brn = 0; brn < 2; brn++) {
        float a = 0.0f;
#pragma unroll 4
        for (int k = 0; k < HID; k++)
            a = fmaf(sh_a[2 * brn][k], Wp_a[k * HID + tid],
                fmaf(sh_a[2 * brn + 1][k], Wxa[k * HID + tid], a));
        v += tanh_(a);
    }
    red0[tid] = v * U[tid * 2 + 0];
    red1[tid] = v * U[tid * 2 + 1];
    __syncthreads();
    for (int s = 128; s > 0; s >>= 1) {
        if (tid < s) { red0[tid] += red0[tid + s]; red1[tid] += red1[tid + s]; }
        __syncthreads();
    }
    if (tid == 0) {
        out[b * 2 + 0] = red0[0] + b_out[0];
        out[b * 2 + 1] = red1[0] + b_out[1];
    }
}

extern "C" void kernel_launch(void* const* d_in, const int* in_sizes, int n_in,
                              void* d_out, int out_size) {
    const float* E    = (const float*)d_in[0];
    const float* Wx1  = (const float*)d_in[1];
    const float* Wh1  = (const float*)d_in[2];
    const float* b1   = (const float*)d_in[3];
    const float* Wx2  = (const float*)d_in[4];
    const float* Wh2  = (const float*)d_in[5];
    const float* b2   = (const float*)d_in[6];
    const float* W_y  = (const float*)d_in[7];
    const float* Wh_a = (const float*)d_in[8];
    const float* Wr_a = (const float*)d_in[9];
    const float* w_a  = (const float*)d_in[10];
    const float* Wt_a = (const float*)d_in[11];
    const float* Wp_a = (const float*)d_in[12];
    const float* Wxa  = (const float*)d_in[13];
    const float* U    = (const float*)d_in[14];
    const float* b_out= (const float*)d_in[15];
    const int* input1 = (const int*)d_in[16];
    const int* input2 = (const int*)d_in[17];
    const int* s1     = (const int*)d_in[18];
    const int* s2     = (const int*)d_in[19];
    float* out = (float*)d_out;

    init_kernel<<<256, 256>>>();
    xg_gemm<<<dim3(240, 8, 2), 256>>>(E, Wx1, b1, Wx2, b2, input1, input2);
    lstm_persist<<<dim3(8, 4, 4), 512>>>(Wh1, Wh2, s1, s2);
    bgemm<<<dim3(240, 2, 4), 256>>>(W_y, Wh_a);
    attn_persist<<<dim3(BSZ / ROWS_A, 2), 256>>>(Wr_a, Wt_a, w_a, s1, s2);
    final_combine<<<BSZ, 256>>>(Wp_a, Wxa, U, b_out, out);
}

// round 14
// speedup vs baseline: 1.0621x; 1.0621x over previous
#include <cuda_runtime.h>
#include <cuda_bf16.h>

#define BSZ 512
#define LSEQ 60
#define DIM 300
#define HID 256
#define G4 1024
#define ROWS_A 8

typedef unsigned long long ull;

// run map: 0=lstm1(x1,s1) 1=lstm2(x2,s2) 2=lstm1(x2,s2) 3=lstm2(x1,s1)
__device__ float g_XG[4][(size_t)BSZ * LSEQ * G4];
__device__ float g_Ybuf[4][(size_t)BSZ * LSEQ * HID];
__device__ float g_h[2][4][BSZ * HID];
__device__ float g_c[4][BSZ * HID];
__device__ float g_WyY[2][(size_t)BSZ * LSEQ * HID];
__device__ float g_WhY2[2][(size_t)BSZ * LSEQ * HID];
__device__ float g_rsel[2][BSZ * HID];
__device__ unsigned g_barL;

__device__ __forceinline__ float tanh_(float x) {
    x = fminf(15.0f, fmaxf(-15.0f, x));
    float e = __expf(2.0f * x);
    return __fdividef(e - 1.0f, e + 1.0f);
}
__device__ __forceinline__ float sigm_(float x) {
    x = fminf(30.0f, fmaxf(-30.0f, x));
    return __fdividef(1.0f, 1.0f + __expf(-x));
}
__device__ __forceinline__ float tanha(float x) {   // HW tanh MUFU op
    float y; asm("tanh.approx.f32 %0, %1;" : "=f"(y) : "f"(x)); return y;
}

// ---- packed f32x2 helpers ----
__device__ __forceinline__ ull pk2(float x, float y) {
    ull r; asm("mov.b64 %0, {%1, %2};" : "=l"(r) : "f"(x), "f"(y)); return r;
}
__device__ __forceinline__ void fma2(ull& d, ull a, ull b) {
    asm("fma.rn.f32x2 %0, %1, %2, %0;" : "+l"(d) : "l"(a), "l"(b));
}
__device__ __forceinline__ void upk2(ull v, float& lo, float& hi) {
    asm("mov.b64 {%0, %1}, %2;" : "=f"(lo), "=f"(hi) : "l"(v));
}

// ---- cp.async helpers ----
__device__ __forceinline__ void cpa16(void* dst, const void* src, int bytes) {
    unsigned d = (unsigned)__cvta_generic_to_shared(dst);
    asm volatile("cp.async.cg.shared.global [%0], [%1], 16, %2;" :: "r"(d), "l"(src), "r"(bytes));
}
__device__ __forceinline__ void cpa_commit() { asm volatile("cp.async.commit_group;"); }
__device__ __forceinline__ void cpa_wait1() { asm volatile("cp.async.wait_group 1;"); }
__device__ __forceinline__ void cpa_wait0() { asm volatile("cp.async.wait_group 0;"); }

// ---- software grid barrier (all CTAs resident by construction) ----
__device__ __forceinline__ void grid_barrier(unsigned target) {
    __syncthreads();
    if (threadIdx.x == 0) {
        __threadfence();
        atomicAdd(&g_barL, 1u);
        while (*(volatile unsigned*)&g_barL < target) {}
        __threadfence();
    }
    __syncthreads();
}

__global__ void init_kernel() {
    int idx = blockIdx.x * blockDim.x + threadIdx.x;
    int stride = gridDim.x * blockDim.x;
    const int n = BSZ * HID;
    float* ph = &g_h[0][0][0];
    float* pc = &g_c[0][0];
    float* ps = &g_rsel[0][0];
    for (int i = idx; i < 8 * n; i += stride) ph[i] = 0.0f;
    for (int i = idx; i < 4 * n; i += stride) pc[i] = 0.0f;
    for (int i = idx; i < 2 * n; i += stride) ps[i] = 0.0f;
    if (idx == 0) g_barL = 0u;
}

// ---------- gather + input projection: XG[run] = E[tok] @ Wx + b ----------
__global__ __launch_bounds__(256) void xg_gemm(
    const float* __restrict__ E,
    const float* __restrict__ Wx1, const float* __restrict__ b1,
    const float* __restrict__ Wx2, const float* __restrict__ b2,
    const int* __restrict__ in1, const int* __restrict__ in2)
{
    const int src = blockIdx.z;
    const int* tok = src == 0 ? in1 : in2;
    const int m0 = blockIdx.x * 128;
    const int n0g = blockIdx.y * 256;
    const bool isW2 = n0g >= G4;
    const float* W = isW2 ? Wx2 : Wx1;
    const float* bias = isW2 ? b2 : b1;
    const int n0 = isW2 ? (n0g - G4) : n0g;
    const int run = isW2 ? (src == 0 ? 3 : 1) : (src == 0 ? 0 : 2);
    float* C = g_XG[run];

    __shared__ float As[2][128][12];
    __shared__ float Bs[2][8][256];

    const int tid = threadIdx.x;
    const int rthr = tid >> 4;
    const int cthr = tid & 15;

    const int arow = tid >> 1;
    const int akq = (tid & 1) * 4;
    const long aBase = (long)tok[m0 + arow] * DIM;

    const int NB = (DIM + 7) / 8;  // 38

    ull acc2[8][8];
#pragma unroll
    for (int i = 0; i < 8; i++)
#pragma unroll
        for (int j = 0; j < 8; j++) acc2[i][j] = 0ull;

    auto loadAB = [&](int buf, int kb) {
        int kA = kb * 8 + akq;
        int remA = DIM - kA;
        int bytesA = remA >= 4 ? 16 : (remA > 0 ? remA * 4 : 0);
        cpa16(&As[buf][arow][akq], &E[aBase + (kA < DIM ? kA : 0)], bytesA);
#pragma unroll
        for (int p = 0; p < 2; p++) {
            int i = p * 256 + tid;
            int kk = i >> 6;
            int c4 = (i & 63) * 4;
            int k = kb * 8 + kk;
            int bytesB = (k < DIM) ? 16 : 0;
            cpa16(&Bs[buf][kk][c4], &W[(long)(k < DIM ? k : 0) * G4 + n0 + c4], bytesB);
        }
    };

    loadAB(0, 0);
    cpa_commit();

    for (int kb = 0; kb < NB; kb++) {
        int buf = kb & 1;
        if (kb + 1 < NB) { loadAB(buf ^ 1, kb + 1); cpa_commit(); cpa_wait1(); }
        else cpa_wait0();
        __syncthreads();
#pragma unroll
        for (int kk = 0; kk < 8; kk++) {
            ull a2[8];
#pragma unroll
            for (int i = 0; i < 8; i++) {
                float a = As[buf][rthr * 8 + i][kk];
                a2[i] = pk2(a, a);
            }
            ull b2v[8];
#pragma unroll
            for (int j = 0; j < 8; j++)
                b2v[j] = *reinterpret_cast<const ull*>(&Bs[buf][kk][2 * cthr + 32 * j]);
#pragma unroll
            for (int i = 0; i < 8; i++)
#pragma unroll
                for (int j = 0; j < 8; j++) fma2(acc2[i][j], a2[i], b2v[j]);
        }
        __syncthreads();
    }

#pragma unroll
    for (int i = 0; i < 8; i++) {
        const long rowOff = (long)(m0 + rthr * 8 + i) * G4 + n0;
#pragma unroll
        for (int j = 0; j < 8; j++) {
            int col = 2 * cthr + 32 * j;
            float lo, hi; upk2(acc2[i][j], lo, hi);
            float2 v = make_float2(lo + bias[n0 + col], hi + bias[n0 + col + 1]);
            *reinterpret_cast<float2*>(&C[rowOff + col]) = v;
        }
    }
}

// ---------- batched [30720,256]x[256,128] products, register-prefetch pipelined ----------
// z=0: WyY[0]=Y(run0)@W_y  z=1: WyY[1]=Y(run2)@W_y
// z=2: WhY2[0]=Y(run1)@Wh_a  z=3: WhY2[1]=Y(run3)@Wh_a
__global__ __launch_bounds__(256, 2) void bgemm(
    const float* __restrict__ W_y, const float* __restrict__ Wh_a)
{
    const int z = blockIdx.z;
    const float* A = g_Ybuf[z == 0 ? 0 : z == 1 ? 2 : z == 2 ? 1 : 3];
    const float* B = (z < 2) ? W_y : Wh_a;
    float* C = (z < 2) ? g_WyY[z] : g_WhY2[z - 2];
    const int m0 = blockIdx.x * 128;
    const int n0 = blockIdx.y * 128;

    __shared__ float As[8][128];
    __shared__ float Bs[8][128];

    const int tid = threadIdx.x;
    const int tm = (tid >> 4) * 8;
    const int tn = (tid & 15) * 8;
    const int lm = tid >> 1;
    const int kq = (tid & 1) * 4;
    const int bkk = tid >> 5;
    const int bn4 = (tid & 31) * 4;

    ull acc2[8][4];
#pragma unroll
    for (int i = 0; i < 8; i++)
#pragma unroll
        for (int j = 0; j < 4; j++) acc2[i][j] = 0ull;

    // prefetch first k-block into registers
    float4 av = *reinterpret_cast<const float4*>(&A[(long)(m0 + lm) * HID + kq]);
    float4 bv = *reinterpret_cast<const float4*>(&B[(long)bkk * HID + n0 + bn4]);

    for (int k0 = 0; k0 < HID; k0 += 8) {
        As[kq + 0][lm] = av.x; As[kq + 1][lm] = av.y;
        As[kq + 2][lm] = av.z; As[kq + 3][lm] = av.w;
        *reinterpret_cast<float4*>(&Bs[bkk][bn4]) = bv;
        __syncthreads();
        if (k0 + 8 < HID) {   // prefetch next block while computing this one
            av = *reinterpret_cast<const float4*>(&A[(long)(m0 + lm) * HID + k0 + 8 + kq]);
            bv = *reinterpret_cast<const float4*>(&B[(long)(k0 + 8 + bkk) * HID + n0 + bn4]);
        }
#pragma unroll
        for (int kk = 0; kk < 8; kk++) {
            float4 t0 = *reinterpret_cast<const float4*>(&As[kk][tm]);
            float4 t1 = *reinterpret_cast<const float4*>(&As[kk][tm + 4]);
            ull a2[8];
            a2[0] = pk2(t0.x, t0.x); a2[1] = pk2(t0.y, t0.y);
            a2[2] = pk2(t0.z, t0.z); a2[3] = pk2(t0.w, t0.w);
            a2[4] = pk2(t1.x, t1.x); a2[5] = pk2(t1.y, t1.y);
            a2[6] = pk2(t1.z, t1.z); a2[7] = pk2(t1.w, t1.w);
            const ull* bp = reinterpret_cast<const ull*>(&Bs[kk][tn]);
            ull b2v[4] = {bp[0], bp[1], bp[2], bp[3]};
#pragma unroll
            for (int i = 0; i < 8; i++)
#pragma unroll
                for (int j = 0; j < 4; j++) fma2(acc2[i][j], a2[i], b2v[j]);
        }
        __syncthreads();
    }
#pragma unroll
    for (int i = 0; i < 8; i++) {
        float* Cp = &C[(long)(m0 + tm + i) * HID + n0 + tn];
#pragma unroll
        for (int j = 0; j < 4; j++) {
            float lo, hi; upk2(acc2[i][j], lo, hi);
            Cp[2 * j] = lo;
            Cp[2 * j + 1] = hi;
        }
    }
}

// ---------- persistent LSTM: all 60 steps in one launch ----------
__global__ __launch_bounds__(512) void lstm_persist(
    const float* __restrict__ Wh1, const float* __restrict__ Wh2,
    const int* __restrict__ s1, const int* __restrict__ s2)
{
    const int run = blockIdx.z;
    const float* Wh = (run == 0 || run == 2) ? Wh1 : Wh2;
    const int* slen = (run == 0 || run == 3) ? s1 : s2;
    const int b0 = blockIdx.x * 64;
    const int h0 = blockIdx.y * 64;
    float* cst = g_c[run];
    float* Y = g_Ybuf[run];
    const float* XG = g_XG[run];

    const int tid = threadIdx.x;
    const int hl = tid & 31;
    const int rg = tid >> 5;   // 0..15 -> rows rg*4..+3

    __shared__ int sh_sl[64];
    __shared__ float As[2][64][20];
    __shared__ float Bs[2][16][256];

    if (tid < 64) sh_sl[tid] = slen[b0 + tid];
    __syncthreads();

    for (int t = 0; t < LSEQ; t++) {
        const float* hin = g_h[t & 1][run];
        float* hout = g_h[(t + 1) & 1][run];

        int anyAct = __syncthreads_or((tid < 64) ? (t < sh_sl[tid]) : 0);
        if (!anyAct) {
#pragma unroll
            for (int p = 0; p < 4; p++) {
                int idx = p * 512 + tid;
                int row = idx >> 5;
                int h = h0 + (idx & 31) * 2;
                int b = b0 + row;
                *reinterpret_cast<float2*>(&hout[b * HID + h]) =
                    *reinterpret_cast<const float2*>(&hin[b * HID + h]);
                *reinterpret_cast<float2*>(&Y[((long)b * LSEQ + t) * HID + h]) =
                    make_float2(0.0f, 0.0f);
            }
            grid_barrier(128u * (unsigned)(t + 1));
            continue;
        }

        auto loadAB = [&](int buf, int kb) {
            int k0 = kb * 16;
            if (tid < 256)
                cpa16(&As[buf][tid >> 2][(tid & 3) * 4],
                      &hin[(b0 + (tid >> 2)) * HID + k0 + (tid & 3) * 4], 16);
#pragma unroll
            for (int p = 0; p < 2; p++) {
                int i = p * 512 + tid;
                int kk = i >> 6;
                int cw = (i & 63) * 4;
                int g = cw >> 6;
                int wn = cw & 63;
                cpa16(&Bs[buf][kk][cw], &Wh[(long)(k0 + kk) * G4 + g * HID + h0 + wn], 16);
            }
        };

        ull acc2[4][4];
#pragma unroll
        for (int i = 0; i < 4; i++)
#pragma unroll
            for (int g = 0; g < 4; g++) acc2[i][g] = 0ull;

        const int NB = HID / 16;  // 16
        loadAB(0, 0);
        cpa_commit();

        for (int kb = 0; kb < NB; kb++) {
            int buf = kb & 1;
            if (kb + 1 < NB) { loadAB(buf ^ 1, kb + 1); cpa_commit(); cpa_wait1(); }
            else cpa_wait0();
            __syncthreads();
#pragma unroll
            for (int kk = 0; kk < 16; kk++) {
                ull a2[4];
#pragma unroll
                for (int rr = 0; rr < 4; rr++) {
                    float a = As[buf][rg * 4 + rr][kk];
                    a2[rr] = pk2(a, a);
                }
                ull b2v[4];
#pragma unroll
                for (int g = 0; g < 4; g++)
                    b2v[g] = *reinterpret_cast<const ull*>(&Bs[buf][kk][g * 64 + hl * 2]);
#pragma unroll
                for (int rr = 0; rr < 4; rr++)
#pragma unroll
                    for (int g = 0; g < 4; g++) fma2(acc2[rr][g], a2[rr], b2v[g]);
            }
            __syncthreads();
        }

        const int h = h0 + hl * 2;
#pragma unroll
        for (int rr = 0; rr < 4; rr++) {
            const int b = b0 + rg * 4 + rr;
            const bool act = t < sh_sl[rg * 4 + rr];
            const float* xg = &XG[((long)b * LSEQ + t) * G4 + h];
            float ix, iy, jx, jy, fx, fy, ox, oy;
            upk2(acc2[rr][0], ix, iy);
            upk2(acc2[rr][1], jx, jy);
            upk2(acc2[rr][2], fx, fy);
            upk2(acc2[rr][3], ox, oy);
            float2 xi = *reinterpret_cast<const float2*>(&xg[0]);
            float2 xj = *reinterpret_cast<const float2*>(&xg[HID]);
            float2 xf = *reinterpret_cast<const float2*>(&xg[2 * HID]);
            float2 xo = *reinterpret_cast<const float2*>(&xg[3 * HID]);
            ix += xi.x; iy += xi.y; jx += xj.x; jy += xj.y;
            fx += xf.x; fy += xf.y; ox += xo.x; oy += xo.y;
            float2 cold = *reinterpret_cast<const float2*>(&cst[b * HID + h]);
            float cnx = cold.x * sigm_(fx + 1.0f) + sigm_(ix) * tanh_(jx);
            float cny = cold.y * sigm_(fy + 1.0f) + sigm_(iy) * tanh_(jy);
            float hnx = tanh_(cnx) * sigm_(ox);
            float hny = tanh_(cny) * sigm_(oy);
            float2 hov, yov;
            if (act) {
                *reinterpret_cast<float2*>(&cst[b * HID + h]) = make_float2(cnx, cny);
                hov = make_float2(hnx, hny);
                yov = hov;
            } else {
                hov = *reinterpret_cast<const float2*>(&hin[b * HID + h]);
                yov = make_float2(0.0f, 0.0f);
            }
            *reinterpret_cast<float2*>(&hout[b * HID + h]) = hov;
            *reinterpret_cast<float2*>(&Y[((long)b * LSEQ + t) * HID + h]) = yov;
        }

        grid_barrier(128u * (unsigned)(t + 1));
    }
}

// ---------- persistent attention: each CTA scans its 8 rows privately (R12 proven) ----------
__global__ __launch_bounds__(256) void attn_persist(
    const float* __restrict__ Wr_a, const float* __restrict__ Wt_a,
    const float* __restrict__ w_a,
    const int* __restrict__ s1, const int* __restrict__ s2)
{
    const int br = blockIdx.y;
    const int b0 = blockIdx.x * ROWS_A;
    const float* Y  = g_Ybuf[br == 0 ? 0 : 2];
    const float* WyY = g_WyY[br];
    const float* WhY2 = g_WhY2[br];
    const int* msel  = br == 0 ? s2 : s1;
    const int* mmask = br == 0 ? s1 : s2;
    float* rsel = g_rsel[br];

    const int tid = threadIdx.x;
    const int lane = tid & 31;
    const int w = tid >> 5;

    __shared__ float sh_r[ROWS_A][HID];
    __shared__ float sh_tmp[ROWS_A][HID];
    __shared__ float sh_rt[ROWS_A][HID];
    __shared__ float sh_sc[ROWS_A][64];
    __shared__ float sh_al[ROWS_A][64];
    __shared__ float sh_wa[HID];
    __shared__ int sh_sel[ROWS_A], sh_ml[ROWS_A], sh_tmax;

    if (tid < ROWS_A) { sh_sel[tid] = msel[b0 + tid]; sh_ml[tid] = mmask[b0 + tid]; }
    sh_wa[tid] = w_a[tid];
#pragma unroll
    for (int rb = 0; rb < ROWS_A; rb++) sh_r[rb][tid] = 0.0f;
    __syncthreads();
    if (tid == 0) {
        int m = 0;
#pragma unroll
        for (int i = 0; i < ROWS_A; i++) m = max(m, sh_sel[i]);
        sh_tmax = m;
    }
    __syncthreads();
    const int tmax = sh_tmax;

    for (int t = 0; t < tmax; t++) {
        {
            float atmp[ROWS_A], art[ROWS_A];
#pragma unroll
            for (int rb = 0; rb < ROWS_A; rb++) { atmp[rb] = 0.0f; art[rb] = 0.0f; }
#pragma unroll 4
            for (int k = 0; k < HID; k++) {
                float wr = Wr_a[k * HID + tid];
                float wt = Wt_a[k * HID + tid];
#pragma unroll
                for (int rb = 0; rb < ROWS_A; rb++) {
                    float rv = sh_r[rb][k];
                    atmp[rb] = fmaf(rv, wr, atmp[rb]);
                    art[rb] = fmaf(rv, wt, art[rb]);
                }
            }
#pragma unroll
            for (int rb = 0; rb < ROWS_A; rb++) {
                sh_tmp[rb][tid] = atmp[rb] + WhY2[((long)(b0 + rb) * LSEQ + t) * HID + tid];
                sh_rt[rb][tid] = art[rb];
            }
        }
        __syncthreads();

        for (int rb = 0; rb < ROWS_A; rb++) {
            if (t >= sh_sel[rb]) continue;
            const int ml = sh_ml[rb];
            const float* WyYb = &WyY[((long)(b0 + rb) * LSEQ) * HID];
            for (int l = w; l < ml; l += 8) {
                float part = 0.0f;
                const float* row = &WyYb[(long)l * HID];
#pragma unroll
                for (int q = 0; q < 8; q++) {
                    int h = lane + q * 32;
                    part = fmaf(tanha(row[h] + sh_tmp[rb][h]), sh_wa[h], part);
                }
#pragma unroll
                for (int off = 16; off > 0; off >>= 1)
                    part += __shfl_xor_sync(0xFFFFFFFFu, part, off);
                if (lane == 0) sh_sc[rb][l] = part;
            }
        }
        __syncthreads();

        if (w < ROWS_A) {
            int rb = w;
            if (t < sh_sel[rb]) {
                const int ml = sh_ml[rb];
                float v0 = (lane < ml) ? sh_sc[rb][lane] : -1e30f;
                float v1 = (lane + 32 < ml) ? sh_sc[rb][lane + 32] : -1e30f;
                float m = fmaxf(v0, v1);
#pragma unroll
                for (int off = 16; off > 0; off >>= 1)
                    m = fmaxf(m, __shfl_xor_sync(0xFFFFFFFFu, m, off));
                float e0 = (lane < ml) ? __expf(v0 - m) : 0.0f;
                float e1 = (lane + 32 < ml) ? __expf(v1 - m) : 0.0f;
                float s = e0 + e1;
#pragma unroll
                for (int off = 16; off > 0; off >>= 1)
                    s += __shfl_xor_sync(0xFFFFFFFFu, s, off);
                float inv = __fdividef(1.0f, s);
                sh_al[rb][lane] = e0 * inv;
                sh_al[rb][lane + 32] = e1 * inv;
            }
        }
        __syncthreads();

        for (int rb = 0; rb < ROWS_A; rb++) {
            if (t >= sh_sel[rb]) continue;
            const int ml = sh_ml[rb];
            const float* Yb = &Y[((long)(b0 + rb) * LSEQ) * HID];
            float acc = 0.0f;
            for (int l = 0; l < ml; l++)
                acc = fmaf(sh_al[rb][l], Yb[(long)l * HID + tid], acc);
            float rn = acc + tanh_(sh_rt[rb][tid]);
            sh_r[rb][tid] = rn;
            if (t == sh_sel[rb] - 1) rsel[(b0 + rb) * HID + tid] = rn;
        }
        __syncthreads();
    }
}

// ---------- final combine ----------
__global__ __launch_bounds__(256) void final_combine(
    const float* __restrict__ Wp_a, const float* __restrict__ Wxa,
    const float* __restrict__ U, const float* __restrict__ b_out,
    float* __restrict__ out)
{
    const int b = blockIdx.x;
    const int tid = threadIdx.x;
    __shared__ float sh_a[4][HID];
    __shared__ float red0[256], red1[256];

    sh_a[0][tid] = g_rsel[0][b * HID + tid];
    sh_a[1][tid] = g_h[0][1][b * HID + tid];   // LSEQ even -> final h in buf 0
    sh_a[2][tid] = g_rsel[1][b * HID + tid];
    sh_a[3][tid] = g_h[0][3][b * HID + tid];
    __syncthreads();

    float v = 0.0f;
#pragma unroll
    for (int brn = 0; brn < 2; brn++) {
        float a = 0.0f;
#pragma unroll 4
        for (int k = 0; k < HID; k++)
            a = fmaf(sh_a[2 * brn][k], Wp_a[k * HID + tid],
                fmaf(sh_a[2 * brn + 1][k], Wxa[k * HID + tid], a));
        v += tanh_(a);
    }
    red0[tid] = v * U[tid * 2 + 0];
    red1[tid] = v * U[tid * 2 + 1];
    __syncthreads();
    for (int s = 128; s > 0; s >>= 1) {
        if (tid < s) { red0[tid] += red0[tid + s]; red1[tid] += red1[tid + s]; }
        __syncthreads();
    }
    if (tid == 0) {
        out[b * 2 + 0] = red0[0] + b_out[0];
        out[b * 2 + 1] = red1[0] + b_out[1];
    }
}

extern "C" void kernel_launch(void* const* d_in, const int* in_sizes, int n_in,
                              void* d_out, int out_size) {
    const float* E    = (const float*)d_in[0];
    const float* Wx1  = (const float*)d_in[1];
    const float* Wh1  = (const float*)d_in[2];
    const float* b1   = (const float*)d_in[3];
    const float* Wx2  = (const float*)d_in[4];
    const float* Wh2  = (const float*)d_in[5];
    const float* b2   = (const float*)d_in[6];
    const float* W_y  = (const float*)d_in[7];
    const float* Wh_a = (const float*)d_in[8];
    const float* Wr_a = (const float*)d_in[9];
    const float* w_a  = (const float*)d_in[10];
    const float* Wt_a = (const float*)d_in[11];
    const float* Wp_a = (const float*)d_in[12];
    const float* Wxa  = (const float*)d_in[13];
    const float* U    = (const float*)d_in[14];
    const float* b_out= (const float*)d_in[15];
    const int* input1 = (const int*)d_in[16];
    const int* input2 = (const int*)d_in[17];
    const int* s1     = (const int*)d_in[18];
    const int* s2     = (const int*)d_in[19];
    float* out = (float*)d_out;

    init_kernel<<<256, 256>>>();
    xg_gemm<<<dim3(240, 8, 2), 256>>>(E, Wx1, b1, Wx2, b2, input1, input2);
    lstm_persist<<<dim3(8, 4, 4), 512>>>(Wh1, Wh2, s1, s2);
    bgemm<<<dim3(240, 2, 4), 256>>>(W_y, Wh_a);
    attn_persist<<<dim3(BSZ / ROWS_A, 2), 256>>>(Wr_a, Wt_a, w_a, s1, s2);
    final_combine<<<BSZ, 256>>>(Wp_a, Wxa, U, b_out, out);
}

// round 15
// speedup vs baseline: 1.1394x; 1.0727x over previous
#include <cuda_runtime.h>
#include <cuda_bf16.h>

#define BSZ 512
#define LSEQ 60
#define DIM 300
#define HID 256
#define G4 1024
#define ROWS_A 8

typedef unsigned long long ull;

// run map: 0=lstm1(x1,s1) 1=lstm2(x2,s2) 2=lstm1(x2,s2) 3=lstm2(x1,s1)
__device__ float g_XG[4][(size_t)BSZ * LSEQ * G4];
__device__ float g_Ybuf[4][(size_t)BSZ * LSEQ * HID];
__device__ float g_h[2][4][BSZ * HID];
__device__ float g_c[4][BSZ * HID];
__device__ float g_WyY[2][(size_t)BSZ * LSEQ * HID];
__device__ float g_WhY2[2][(size_t)BSZ * LSEQ * HID];
__device__ float g_rsel[2][BSZ * HID];
__device__ unsigned g_barL;

__device__ __forceinline__ float tanh_(float x) {
    x = fminf(15.0f, fmaxf(-15.0f, x));
    float e = __expf(2.0f * x);
    return __fdividef(e - 1.0f, e + 1.0f);
}
__device__ __forceinline__ float sigm_(float x) {
    x = fminf(30.0f, fmaxf(-30.0f, x));
    return __fdividef(1.0f, 1.0f + __expf(-x));
}
__device__ __forceinline__ float tanha(float x) {   // HW tanh MUFU op
    float y; asm("tanh.approx.f32 %0, %1;" : "=f"(y) : "f"(x)); return y;
}

// ---- packed f32x2 helpers ----
__device__ __forceinline__ ull pk2(float x, float y) {
    ull r; asm("mov.b64 %0, {%1, %2};" : "=l"(r) : "f"(x), "f"(y)); return r;
}
__device__ __forceinline__ void fma2(ull& d, ull a, ull b) {
    asm("fma.rn.f32x2 %0, %1, %2, %0;" : "+l"(d) : "l"(a), "l"(b));
}
__device__ __forceinline__ void upk2(ull v, float& lo, float& hi) {
    asm("mov.b64 {%0, %1}, %2;" : "=f"(lo), "=f"(hi) : "l"(v));
}

// ---- cp.async helpers ----
__device__ __forceinline__ void cpa16(void* dst, const void* src, int bytes) {
    unsigned d = (unsigned)__cvta_generic_to_shared(dst);
    asm volatile("cp.async.cg.shared.global [%0], [%1], 16, %2;" :: "r"(d), "l"(src), "r"(bytes));
}
__device__ __forceinline__ void cpa_commit() { asm volatile("cp.async.commit_group;"); }
__device__ __forceinline__ void cpa_wait1() { asm volatile("cp.async.wait_group 1;"); }
__device__ __forceinline__ void cpa_wait0() { asm volatile("cp.async.wait_group 0;"); }

// ---- software grid barrier (all CTAs resident by construction) ----
__device__ __forceinline__ void grid_barrier(unsigned target) {
    __syncthreads();
    if (threadIdx.x == 0) {
        __threadfence();
        atomicAdd(&g_barL, 1u);
        while (*(volatile unsigned*)&g_barL < target) {}
        __threadfence();
    }
    __syncthreads();
}

__global__ void init_kernel() {
    int idx = blockIdx.x * blockDim.x + threadIdx.x;
    int stride = gridDim.x * blockDim.x;
    const int n = BSZ * HID;
    float* ph = &g_h[0][0][0];
    float* pc = &g_c[0][0];
    float* ps = &g_rsel[0][0];
    for (int i = idx; i < 8 * n; i += stride) ph[i] = 0.0f;
    for (int i = idx; i < 4 * n; i += stride) pc[i] = 0.0f;
    for (int i = idx; i < 2 * n; i += stride) ps[i] = 0.0f;
    if (idx == 0) g_barL = 0u;
}

// ---------- gather + input projection: XG[run] = E[tok] @ Wx + b ----------
// 128x128 tile, 8-row x 4-col-pair microtile (64 acc regs), register-prefetch pipeline.
// grid (240, 16, 2): y spans [Wx1|Wx2] 2048 cols.
__global__ __launch_bounds__(256, 2) void xg_gemm(
    const float* __restrict__ E,
    const float* __restrict__ Wx1, const float* __restrict__ b1,
    const float* __restrict__ Wx2, const float* __restrict__ b2,
    const int* __restrict__ in1, const int* __restrict__ in2)
{
    const int src = blockIdx.z;
    const int* tok = src == 0 ? in1 : in2;
    const int m0 = blockIdx.x * 128;
    const int n0g = blockIdx.y * 128;
    const bool isW2 = n0g >= G4;
    const float* W = isW2 ? Wx2 : Wx1;
    const float* bias = isW2 ? b2 : b1;
    const int n0 = isW2 ? (n0g - G4) : n0g;
    const int run = isW2 ? (src == 0 ? 3 : 1) : (src == 0 ? 0 : 2);
    float* C = g_XG[run];

    __shared__ float As[8][128];
    __shared__ float Bs[8][128];

    const int tid = threadIdx.x;
    const int tm = (tid >> 4) * 8;       // 8 rows
    const int cthr = tid & 15;           // col pairs 2*cthr + 32*j, j=0..3
    const int lm = tid >> 1;             // A row for loading
    const int kq = (tid & 1) * 4;        // A k-quad for loading
    const int bkk = tid >> 5;            // B k-row for loading
    const int bn4 = (tid & 31) * 4;      // B col-quad for loading
    const long aBase = (long)tok[m0 + lm] * DIM;

    const int NB = (DIM + 7) / 8;        // 38 (last block half-tail)

    ull acc2[8][4];
#pragma unroll
    for (int i = 0; i < 8; i++)
#pragma unroll
        for (int j = 0; j < 4; j++) acc2[i][j] = 0ull;

    // register prefetch of k-block 0 (all float4 accesses 4-aligned; 300 % 4 == 0)
    float4 av, bv;
    {
        int kA = kq;                      // < 300 always for block 0
        av = *reinterpret_cast<const float4*>(&E[aBase + kA]);
        bv = *reinterpret_cast<const float4*>(&W[(long)bkk * G4 + n0 + bn4]);
    }

    for (int kb = 0; kb < NB; kb++) {
        As[kq + 0][lm] = av.x; As[kq + 1][lm] = av.y;
        As[kq + 2][lm] = av.z; As[kq + 3][lm] = av.w;
        *reinterpret_cast<float4*>(&Bs[bkk][bn4]) = bv;
        __syncthreads();
        if (kb + 1 < NB) {               // prefetch next block (zero-fill past DIM)
            int kA = (kb + 1) * 8 + kq;
            av = (kA < DIM) ? *reinterpret_cast<const float4*>(&E[aBase + kA])
                            : make_float4(0.f, 0.f, 0.f, 0.f);
            int kB = (kb + 1) * 8 + bkk;
            bv = (kB < DIM) ? *reinterpret_cast<const float4*>(&W[(long)kB * G4 + n0 + bn4])
                            : make_float4(0.f, 0.f, 0.f, 0.f);
        }
#pragma unroll
        for (int kk = 0; kk < 8; kk++) {
            float4 t0 = *reinterpret_cast<const float4*>(&As[kk][tm]);
            float4 t1 = *reinterpret_cast<const float4*>(&As[kk][tm + 4]);
            ull a2[8];
            a2[0] = pk2(t0.x, t0.x); a2[1] = pk2(t0.y, t0.y);
            a2[2] = pk2(t0.z, t0.z); a2[3] = pk2(t0.w, t0.w);
            a2[4] = pk2(t1.x, t1.x); a2[5] = pk2(t1.y, t1.y);
            a2[6] = pk2(t1.z, t1.z); a2[7] = pk2(t1.w, t1.w);
            ull b2v[4];
#pragma unroll
            for (int j = 0; j < 4; j++)
                b2v[j] = *reinterpret_cast<const ull*>(&Bs[kk][2 * cthr + 32 * j]);
#pragma unroll
            for (int i = 0; i < 8; i++)
#pragma unroll
                for (int j = 0; j < 4; j++) fma2(acc2[i][j], a2[i], b2v[j]);
        }
        __syncthreads();
    }

#pragma unroll
    for (int i = 0; i < 8; i++) {
        const long rowOff = (long)(m0 + tm + i) * G4 + n0;
#pragma unroll
        for (int j = 0; j < 4; j++) {
            int col = 2 * cthr + 32 * j;
            float lo, hi; upk2(acc2[i][j], lo, hi);
            float2 v = make_float2(lo + bias[n0 + col], hi + bias[n0 + col + 1]);
            *reinterpret_cast<float2*>(&C[rowOff + col]) = v;
        }
    }
}

// ---------- batched [30720,256]x[256,128] products, register-prefetch pipelined ----------
__global__ __launch_bounds__(256, 2) void bgemm(
    const float* __restrict__ W_y, const float* __restrict__ Wh_a)
{
    const int z = blockIdx.z;
    const float* A = g_Ybuf[z == 0 ? 0 : z == 1 ? 2 : z == 2 ? 1 : 3];
    const float* B = (z < 2) ? W_y : Wh_a;
    float* C = (z < 2) ? g_WyY[z] : g_WhY2[z - 2];
    const int m0 = blockIdx.x * 128;
    const int n0 = blockIdx.y * 128;

    __shared__ float As[8][128];
    __shared__ float Bs[8][128];

    const int tid = threadIdx.x;
    const int tm = (tid >> 4) * 8;
    const int tn = (tid & 15) * 8;
    const int lm = tid >> 1;
    const int kq = (tid & 1) * 4;
    const int bkk = tid >> 5;
    const int bn4 = (tid & 31) * 4;

    ull acc2[8][4];
#pragma unroll
    for (int i = 0; i < 8; i++)
#pragma unroll
        for (int j = 0; j < 4; j++) acc2[i][j] = 0ull;

    float4 av = *reinterpret_cast<const float4*>(&A[(long)(m0 + lm) * HID + kq]);
    float4 bv = *reinterpret_cast<const float4*>(&B[(long)bkk * HID + n0 + bn4]);

    for (int k0 = 0; k0 < HID; k0 += 8) {
        As[kq + 0][lm] = av.x; As[kq + 1][lm] = av.y;
        As[kq + 2][lm] = av.z; As[kq + 3][lm] = av.w;
        *reinterpret_cast<float4*>(&Bs[bkk][bn4]) = bv;
        __syncthreads();
        if (k0 + 8 < HID) {
            av = *reinterpret_cast<const float4*>(&A[(long)(m0 + lm) * HID + k0 + 8 + kq]);
            bv = *reinterpret_cast<const float4*>(&B[(long)(k0 + 8 + bkk) * HID + n0 + bn4]);
        }
#pragma unroll
        for (int kk = 0; kk < 8; kk++) {
            float4 t0 = *reinterpret_cast<const float4*>(&As[kk][tm]);
            float4 t1 = *reinterpret_cast<const float4*>(&As[kk][tm + 4]);
            ull a2[8];
            a2[0] = pk2(t0.x, t0.x); a2[1] = pk2(t0.y, t0.y);
            a2[2] = pk2(t0.z, t0.z); a2[3] = pk2(t0.w, t0.w);
            a2[4] = pk2(t1.x, t1.x); a2[5] = pk2(t1.y, t1.y);
            a2[6] = pk2(t1.z, t1.z); a2[7] = pk2(t1.w, t1.w);
            const ull* bp = reinterpret_cast<const ull*>(&Bs[kk][tn]);
            ull b2v[4] = {bp[0], bp[1], bp[2], bp[3]};
#pragma unroll
            for (int i = 0; i < 8; i++)
#pragma unroll
                for (int j = 0; j < 4; j++) fma2(acc2[i][j], a2[i], b2v[j]);
        }
        __syncthreads();
    }
#pragma unroll
    for (int i = 0; i < 8; i++) {
        float* Cp = &C[(long)(m0 + tm + i) * HID + n0 + tn];
#pragma unroll
        for (int j = 0; j < 4; j++) {
            float lo, hi; upk2(acc2[i][j], lo, hi);
            Cp[2 * j] = lo;
            Cp[2 * j + 1] = hi;
        }
    }
}

// ---------- persistent LSTM: all 60 steps in one launch ----------
__global__ __launch_bounds__(512) void lstm_persist(
    const float* __restrict__ Wh1, const float* __restrict__ Wh2,
    const int* __restrict__ s1, const int* __restrict__ s2)
{
    const int run = blockIdx.z;
    const float* Wh = (run == 0 || run == 2) ? Wh1 : Wh2;
    const int* slen = (run == 0 || run == 3) ? s1 : s2;
    const int b0 = blockIdx.x * 64;
    const int h0 = blockIdx.y * 64;
    float* cst = g_c[run];
    float* Y = g_Ybuf[run];
    const float* XG = g_XG[run];

    const int tid = threadIdx.x;
    const int hl = tid & 31;
    const int rg = tid >> 5;   // 0..15 -> rows rg*4..+3

    __shared__ int sh_sl[64];
    __shared__ float As[2][64][20];
    __shared__ float Bs[2][16][256];

    if (tid < 64) sh_sl[tid] = slen[b0 + tid];
    __syncthreads();

    for (int t = 0; t < LSEQ; t++) {
        const float* hin = g_h[t & 1][run];
        float* hout = g_h[(t + 1) & 1][run];

        int anyAct = __syncthreads_or((tid < 64) ? (t < sh_sl[tid]) : 0);
        if (!anyAct) {
#pragma unroll
            for (int p = 0; p < 4; p++) {
                int idx = p * 512 + tid;
                int row = idx >> 5;
                int h = h0 + (idx & 31) * 2;
                int b = b0 + row;
                *reinterpret_cast<float2*>(&hout[b * HID + h]) =
                    *reinterpret_cast<const float2*>(&hin[b * HID + h]);
                *reinterpret_cast<float2*>(&Y[((long)b * LSEQ + t) * HID + h]) =
                    make_float2(0.0f, 0.0f);
            }
            grid_barrier(128u * (unsigned)(t + 1));
            continue;
        }

        auto loadAB = [&](int buf, int kb) {
            int k0 = kb * 16;
            if (tid < 256)
                cpa16(&As[buf][tid >> 2][(tid & 3) * 4],
                      &hin[(b0 + (tid >> 2)) * HID + k0 + (tid & 3) * 4], 16);
#pragma unroll
            for (int p = 0; p < 2; p++) {
                int i = p * 512 + tid;
                int kk = i >> 6;
                int cw = (i & 63) * 4;
                int g = cw >> 6;
                int wn = cw & 63;
                cpa16(&Bs[buf][kk][cw], &Wh[(long)(k0 + kk) * G4 + g * HID + h0 + wn], 16);
            }
        };

        ull acc2[4][4];
#pragma unroll
        for (int i = 0; i < 4; i++)
#pragma unroll
            for (int g = 0; g < 4; g++) acc2[i][g] = 0ull;

        const int NB = HID / 16;  // 16
        loadAB(0, 0);
        cpa_commit();

        for (int kb = 0; kb < NB; kb++) {
            int buf = kb & 1;
            if (kb + 1 < NB) { loadAB(buf ^ 1, kb + 1); cpa_commit(); cpa_wait1(); }
            else cpa_wait0();
            __syncthreads();
#pragma unroll
            for (int kk = 0; kk < 16; kk++) {
                ull a2[4];
#pragma unroll
                for (int rr = 0; rr < 4; rr++) {
                    float a = As[buf][rg * 4 + rr][kk];
                    a2[rr] = pk2(a, a);
                }
                ull b2v[4];
#pragma unroll
                for (int g = 0; g < 4; g++)
                    b2v[g] = *reinterpret_cast<const ull*>(&Bs[buf][kk][g * 64 + hl * 2]);
#pragma unroll
                for (int rr = 0; rr < 4; rr++)
#pragma unroll
                    for (int g = 0; g < 4; g++) fma2(acc2[rr][g], a2[rr], b2v[g]);
            }
            __syncthreads();
        }

        const int h = h0 + hl * 2;
#pragma unroll
        for (int rr = 0; rr < 4; rr++) {
            const int b = b0 + rg * 4 + rr;
            const bool act = t < sh_sl[rg * 4 + rr];
            const float* xg = &XG[((long)b * LSEQ + t) * G4 + h];
            float ix, iy, jx, jy, fx, fy, ox, oy;
            upk2(acc2[rr][0], ix, iy);
            upk2(acc2[rr][1], jx, jy);
            upk2(acc2[rr][2], fx, fy);
            upk2(acc2[rr][3], ox, oy);
            float2 xi = *reinterpret_cast<const float2*>(&xg[0]);
            float2 xj = *reinterpret_cast<const float2*>(&xg[HID]);
            float2 xf = *reinterpret_cast<const float2*>(&xg[2 * HID]);
            float2 xo = *reinterpret_cast<const float2*>(&xg[3 * HID]);
            ix += xi.x; iy += xi.y; jx += xj.x; jy += xj.y;
            fx += xf.x; fy += xf.y; ox += xo.x; oy += xo.y;
            float2 cold = *reinterpret_cast<const float2*>(&cst[b * HID + h]);
            float cnx = cold.x * sigm_(fx + 1.0f) + sigm_(ix) * tanh_(jx);
            float cny = cold.y * sigm_(fy + 1.0f) + sigm_(iy) * tanh_(jy);
            float hnx = tanh_(cnx) * sigm_(ox);
            float hny = tanh_(cny) * sigm_(oy);
            float2 hov, yov;
            if (act) {
                *reinterpret_cast<float2*>(&cst[b * HID + h]) = make_float2(cnx, cny);
                hov = make_float2(hnx, hny);
                yov = hov;
            } else {
                hov = *reinterpret_cast<const float2*>(&hin[b * HID + h]);
                yov = make_float2(0.0f, 0.0f);
            }
            *reinterpret_cast<float2*>(&hout[b * HID + h]) = hov;
            *reinterpret_cast<float2*>(&Y[((long)b * LSEQ + t) * HID + h]) = yov;
        }

        grid_barrier(128u * (unsigned)(t + 1));
    }
}

// ---------- persistent attention: each CTA scans its 8 rows privately (R12 proven) ----------
__global__ __launch_bounds__(256) void attn_persist(
    const float* __restrict__ Wr_a, const float* __restrict__ Wt_a,
    const float* __restrict__ w_a,
    const int* __restrict__ s1, const int* __restrict__ s2)
{
    const int br = blockIdx.y;
    const int b0 = blockIdx.x * ROWS_A;
    const float* Y  = g_Ybuf[br == 0 ? 0 : 2];
    const float* WyY = g_WyY[br];
    const float* WhY2 = g_WhY2[br];
    const int* msel  = br == 0 ? s2 : s1;
    const int* mmask = br == 0 ? s1 : s2;
    float* rsel = g_rsel[br];

    const int tid = threadIdx.x;
    const int lane = tid & 31;
    const int w = tid >> 5;

    __shared__ float sh_r[ROWS_A][HID];
    __shared__ float sh_tmp[ROWS_A][HID];
    __shared__ float sh_rt[ROWS_A][HID];
    __shared__ float sh_sc[ROWS_A][64];
    __shared__ float sh_al[ROWS_A][64];
    __shared__ float sh_wa[HID];
    __shared__ int sh_sel[ROWS_A], sh_ml[ROWS_A], sh_tmax;

    if (tid < ROWS_A) { sh_sel[tid] = msel[b0 + tid]; sh_ml[tid] = mmask[b0 + tid]; }
    sh_wa[tid] = w_a[tid];
#pragma unroll
    for (int rb = 0; rb < ROWS_A; rb++) sh_r[rb][tid] = 0.0f;
    __syncthreads();
    if (tid == 0) {
        int m = 0;
#pragma unroll
        for (int i = 0; i < ROWS_A; i++) m = max(m, sh_sel[i]);
        sh_tmax = m;
    }
    __syncthreads();
    const int tmax = sh_tmax;

    for (int t = 0; t < tmax; t++) {
        {
            float atmp[ROWS_A], art[ROWS_A];
#pragma unroll
            for (int rb = 0; rb < ROWS_A; rb++) { atmp[rb] = 0.0f; art[rb] = 0.0f; }
#pragma unroll 4
            for (int k = 0; k < HID; k++) {
                float wr = Wr_a[k * HID + tid];
                float wt = Wt_a[k * HID + tid];
#pragma unroll
                for (int rb = 0; rb < ROWS_A; rb++) {
                    float rv = sh_r[rb][k];
                    atmp[rb] = fmaf(rv, wr, atmp[rb]);
                    art[rb] = fmaf(rv, wt, art[rb]);
                }
            }
#pragma unroll
            for (int rb = 0; rb < ROWS_A; rb++) {
                sh_tmp[rb][tid] = atmp[rb] + WhY2[((long)(b0 + rb) * LSEQ + t) * HID + tid];
                sh_rt[rb][tid] = art[rb];
            }
        }
        __syncthreads();

        for (int rb = 0; rb < ROWS_A; rb++) {
            if (t >= sh_sel[rb]) continue;
            const int ml = sh_ml[rb];
            const float* WyYb = &WyY[((long)(b0 + rb) * LSEQ) * HID];
            for (int l = w; l < ml; l += 8) {
                float part = 0.0f;
                const float* row = &WyYb[(long)l * HID];
#pragma unroll
                for (int q = 0; q < 8; q++) {
                    int h = lane + q * 32;
                    part = fmaf(tanha(row[h] + sh_tmp[rb][h]), sh_wa[h], part);
                }
#pragma unroll
                for (int off = 16; off > 0; off >>= 1)
                    part += __shfl_xor_sync(0xFFFFFFFFu, part, off);
                if (lane == 0) sh_sc[rb][l] = part;
            }
        }
        __syncthreads();

        if (w < ROWS_A) {
            int rb = w;
            if (t < sh_sel[rb]) {
                const int ml = sh_ml[rb];
                float v0 = (lane < ml) ? sh_sc[rb][lane] : -1e30f;
                float v1 = (lane + 32 < ml) ? sh_sc[rb][lane + 32] : -1e30f;
                float m = fmaxf(v0, v1);
#pragma unroll
                for (int off = 16; off > 0; off >>= 1)
                    m = fmaxf(m, __shfl_xor_sync(0xFFFFFFFFu, m, off));
                float e0 = (lane < ml) ? __expf(v0 - m) : 0.0f;
                float e1 = (lane + 32 < ml) ? __expf(v1 - m) : 0.0f;
                float s = e0 + e1;
#pragma unroll
                for (int off = 16; off > 0; off >>= 1)
                    s += __shfl_xor_sync(0xFFFFFFFFu, s, off);
                float inv = __fdividef(1.0f, s);
                sh_al[rb][lane] = e0 * inv;
                sh_al[rb][lane + 32] = e1 * inv;
            }
        }
        __syncthreads();

        for (int rb = 0; rb < ROWS_A; rb++) {
            if (t >= sh_sel[rb]) continue;
            const int ml = sh_ml[rb];
            const float* Yb = &Y[((long)(b0 + rb) * LSEQ) * HID];
            float acc = 0.0f;
            for (int l = 0; l < ml; l++)
                acc = fmaf(sh_al[rb][l], Yb[(long)l * HID + tid], acc);
            float rn = acc + tanh_(sh_rt[rb][tid]);
            sh_r[rb][tid] = rn;
            if (t == sh_sel[rb] - 1) rsel[(b0 + rb) * HID + tid] = rn;
        }
        __syncthreads();
    }
}

// ---------- final combine ----------
__global__ __launch_bounds__(256) void final_combine(
    const float* __restrict__ Wp_a, const float* __restrict__ Wxa,
    const float* __restrict__ U, const float* __restrict__ b_out,
    float* __restrict__ out)
{
    const int b = blockIdx.x;
    const int tid = threadIdx.x;
    __shared__ float sh_a[4][HID];
    __shared__ float red0[256], red1[256];

    sh_a[0][tid] = g_rsel[0][b * HID + tid];
    sh_a[1][tid] = g_h[0][1][b * HID + tid];   // LSEQ even -> final h in buf 0
    sh_a[2][tid] = g_rsel[1][b * HID + tid];
    sh_a[3][tid] = g_h[0][3][b * HID + tid];
    __syncthreads();

    float v = 0.0f;
#pragma unroll
    for (int brn = 0; brn < 2; brn++) {
        float a = 0.0f;
#pragma unroll 4
        for (int k = 0; k < HID; k++)
            a = fmaf(sh_a[2 * brn][k], Wp_a[k * HID + tid],
                fmaf(sh_a[2 * brn + 1][k], Wxa[k * HID + tid], a));
        v += tanh_(a);
    }
    red0[tid] = v * U[tid * 2 + 0];
    red1[tid] = v * U[tid * 2 + 1];
    __syncthreads();
    for (int s = 128; s > 0; s >>= 1) {
        if (tid < s) { red0[tid] += red0[tid + s]; red1[tid] += red1[tid + s]; }
        __syncthreads();
    }
    if (tid == 0) {
        out[b * 2 + 0] = red0[0] + b_out[0];
        out[b * 2 + 1] = red1[0] + b_out[1];
    }
}

extern "C" void kernel_launch(void* const* d_in, const int* in_sizes, int n_in,
                              void* d_out, int out_size) {
    const float* E    = (const float*)d_in[0];
    const float* Wx1  = (const float*)d_in[1];
    const float* Wh1  = (const float*)d_in[2];
    const float* b1   = (const float*)d_in[3];
    const float* Wx2  = (const float*)d_in[4];
    const float* Wh2  = (const float*)d_in[5];
    const float* b2   = (const float*)d_in[6];
    const float* W_y  = (const float*)d_in[7];
    const float* Wh_a = (const float*)d_in[8];
    const float* Wr_a = (const float*)d_in[9];
    const float* w_a  = (const float*)d_in[10];
    const float* Wt_a = (const float*)d_in[11];
    const float* Wp_a = (const float*)d_in[12];
    const float* Wxa  = (const float*)d_in[13];
    const float* U    = (const float*)d_in[14];
    const float* b_out= (const float*)d_in[15];
    const int* input1 = (const int*)d_in[16];
    const int* input2 = (const int*)d_in[17];
    const int* s1     = (const int*)d_in[18];
    const int* s2     = (const int*)d_in[19];
    float* out = (float*)d_out;

    init_kernel<<<256, 256>>>();
    xg_gemm<<<dim3(240, 16, 2), 256>>>(E, Wx1, b1, Wx2, b2, input1, input2);
    lstm_persist<<<dim3(8, 4, 4), 512>>>(Wh1, Wh2, s1, s2);
    bgemm<<<dim3(240, 2, 4), 256>>>(W_y, Wh_a);
    attn_persist<<<dim3(BSZ / ROWS_A, 2), 256>>>(Wr_a, Wt_a, w_a, s1, s2);
    final_combine<<<BSZ, 256>>>(Wp_a, Wxa, U, b_out, out);
}

// round 16
// speedup vs baseline: 1.2260x; 1.0760x over previous
#include <cuda_runtime.h>
#include <cuda_bf16.h>

#define BSZ 512
#define LSEQ 60
#define DIM 300
#define HID 256
#define G4 1024
#define ROWS_A 8

typedef unsigned long long ull;

// run map: 0=lstm1(x1,s1) 1=lstm2(x2,s2) 2=lstm1(x2,s2) 3=lstm2(x1,s1)
__device__ float g_XG[4][(size_t)BSZ * LSEQ * G4];
__device__ float g_Ybuf[4][(size_t)BSZ * LSEQ * HID];
__device__ float g_h[2][4][BSZ * HID];
__device__ float g_c[4][BSZ * HID];
__device__ float g_WyY[2][(size_t)BSZ * LSEQ * HID];
__device__ float g_WhY2[2][(size_t)BSZ * LSEQ * HID];
__device__ float g_rsel[2][BSZ * HID];
__device__ unsigned g_barL;

__device__ __forceinline__ float tanh_(float x) {
    x = fminf(15.0f, fmaxf(-15.0f, x));
    float e = __expf(2.0f * x);
    return __fdividef(e - 1.0f, e + 1.0f);
}
__device__ __forceinline__ float sigm_(float x) {
    x = fminf(30.0f, fmaxf(-30.0f, x));
    return __fdividef(1.0f, 1.0f + __expf(-x));
}
__device__ __forceinline__ float tanha(float x) {   // HW tanh MUFU op
    float y; asm("tanh.approx.f32 %0, %1;" : "=f"(y) : "f"(x)); return y;
}

// ---- packed f32x2 helpers ----
__device__ __forceinline__ ull pk2(float x, float y) {
    ull r; asm("mov.b64 %0, {%1, %2};" : "=l"(r) : "f"(x), "f"(y)); return r;
}
__device__ __forceinline__ void fma2(ull& d, ull a, ull b) {
    asm("fma.rn.f32x2 %0, %1, %2, %0;" : "+l"(d) : "l"(a), "l"(b));
}
__device__ __forceinline__ void upk2(ull v, float& lo, float& hi) {
    asm("mov.b64 {%0, %1}, %2;" : "=f"(lo), "=f"(hi) : "l"(v));
}

// ---- cp.async helpers ----
__device__ __forceinline__ void cpa16(void* dst, const void* src, int bytes) {
    unsigned d = (unsigned)__cvta_generic_to_shared(dst);
    asm volatile("cp.async.cg.shared.global [%0], [%1], 16, %2;" :: "r"(d), "l"(src), "r"(bytes));
}
__device__ __forceinline__ void cpa_commit() { asm volatile("cp.async.commit_group;"); }
__device__ __forceinline__ void cpa_wait1() { asm volatile("cp.async.wait_group 1;"); }
__device__ __forceinline__ void cpa_wait0() { asm volatile("cp.async.wait_group 0;"); }

// ---- software grid barrier (all CTAs resident by construction) ----
__device__ __forceinline__ void grid_barrier(unsigned target) {
    __syncthreads();
    if (threadIdx.x == 0) {
        __threadfence();
        atomicAdd(&g_barL, 1u);
        while (*(volatile unsigned*)&g_barL < target) {}
        __threadfence();
    }
    __syncthreads();
}

__global__ void init_kernel() {
    int idx = blockIdx.x * blockDim.x + threadIdx.x;
    int stride = gridDim.x * blockDim.x;
    const int n = BSZ * HID;
    float* ph = &g_h[0][0][0];
    float* pc = &g_c[0][0];
    float* ps = &g_rsel[0][0];
    for (int i = idx; i < 8 * n; i += stride) ph[i] = 0.0f;
    for (int i = idx; i < 4 * n; i += stride) pc[i] = 0.0f;
    for (int i = idx; i < 2 * n; i += stride) ps[i] = 0.0f;
    if (idx == 0) g_barL = 0u;
}

// ---------- gather + input projection: XG[run] = E[tok] @ Wx + b ----------
// 128x128 tile, 8-row x 4-col-pair microtile, register-prefetch pipeline.
__global__ __launch_bounds__(256, 2) void xg_gemm(
    const float* __restrict__ E,
    const float* __restrict__ Wx1, const float* __restrict__ b1,
    const float* __restrict__ Wx2, const float* __restrict__ b2,
    const int* __restrict__ in1, const int* __restrict__ in2)
{
    const int src = blockIdx.z;
    const int* tok = src == 0 ? in1 : in2;
    const int m0 = blockIdx.x * 128;
    const int n0g = blockIdx.y * 128;
    const bool isW2 = n0g >= G4;
    const float* W = isW2 ? Wx2 : Wx1;
    const float* bias = isW2 ? b2 : b1;
    const int n0 = isW2 ? (n0g - G4) : n0g;
    const int run = isW2 ? (src == 0 ? 3 : 1) : (src == 0 ? 0 : 2);
    float* C = g_XG[run];

    __shared__ float As[8][128];
    __shared__ float Bs[8][128];

    const int tid = threadIdx.x;
    const int tm = (tid >> 4) * 8;
    const int cthr = tid & 15;
    const int lm = tid >> 1;
    const int kq = (tid & 1) * 4;
    const int bkk = tid >> 5;
    const int bn4 = (tid & 31) * 4;
    const long aBase = (long)tok[m0 + lm] * DIM;

    const int NB = (DIM + 7) / 8;        // 38

    ull acc2[8][4];
#pragma unroll
    for (int i = 0; i < 8; i++)
#pragma unroll
        for (int j = 0; j < 4; j++) acc2[i][j] = 0ull;

    float4 av, bv;
    av = *reinterpret_cast<const float4*>(&E[aBase + kq]);
    bv = *reinterpret_cast<const float4*>(&W[(long)bkk * G4 + n0 + bn4]);

    for (int kb = 0; kb < NB; kb++) {
        As[kq + 0][lm] = av.x; As[kq + 1][lm] = av.y;
        As[kq + 2][lm] = av.z; As[kq + 3][lm] = av.w;
        *reinterpret_cast<float4*>(&Bs[bkk][bn4]) = bv;
        __syncthreads();
        if (kb + 1 < NB) {
            int kA = (kb + 1) * 8 + kq;
            av = (kA < DIM) ? *reinterpret_cast<const float4*>(&E[aBase + kA])
                            : make_float4(0.f, 0.f, 0.f, 0.f);
            int kB = (kb + 1) * 8 + bkk;
            bv = (kB < DIM) ? *reinterpret_cast<const float4*>(&W[(long)kB * G4 + n0 + bn4])
                            : make_float4(0.f, 0.f, 0.f, 0.f);
        }
#pragma unroll
        for (int kk = 0; kk < 8; kk++) {
            float4 t0 = *reinterpret_cast<const float4*>(&As[kk][tm]);
            float4 t1 = *reinterpret_cast<const float4*>(&As[kk][tm + 4]);
            ull a2[8];
            a2[0] = pk2(t0.x, t0.x); a2[1] = pk2(t0.y, t0.y);
            a2[2] = pk2(t0.z, t0.z); a2[3] = pk2(t0.w, t0.w);
            a2[4] = pk2(t1.x, t1.x); a2[5] = pk2(t1.y, t1.y);
            a2[6] = pk2(t1.z, t1.z); a2[7] = pk2(t1.w, t1.w);
            ull b2v[4];
#pragma unroll
            for (int j = 0; j < 4; j++)
                b2v[j] = *reinterpret_cast<const ull*>(&Bs[kk][2 * cthr + 32 * j]);
#pragma unroll
            for (int i = 0; i < 8; i++)
#pragma unroll
                for (int j = 0; j < 4; j++) fma2(acc2[i][j], a2[i], b2v[j]);
        }
        __syncthreads();
    }

#pragma unroll
    for (int i = 0; i < 8; i++) {
        const long rowOff = (long)(m0 + tm + i) * G4 + n0;
#pragma unroll
        for (int j = 0; j < 4; j++) {
            int col = 2 * cthr + 32 * j;
            float lo, hi; upk2(acc2[i][j], lo, hi);
            float2 v = make_float2(lo + bias[n0 + col], hi + bias[n0 + col + 1]);
            *reinterpret_cast<float2*>(&C[rowOff + col]) = v;
        }
    }
}

// ---------- batched [30720,256]x[256,128] products, register-prefetch pipelined ----------
__global__ __launch_bounds__(256, 2) void bgemm(
    const float* __restrict__ W_y, const float* __restrict__ Wh_a)
{
    const int z = blockIdx.z;
    const float* A = g_Ybuf[z == 0 ? 0 : z == 1 ? 2 : z == 2 ? 1 : 3];
    const float* B = (z < 2) ? W_y : Wh_a;
    float* C = (z < 2) ? g_WyY[z] : g_WhY2[z - 2];
    const int m0 = blockIdx.x * 128;
    const int n0 = blockIdx.y * 128;

    __shared__ float As[8][128];
    __shared__ float Bs[8][128];

    const int tid = threadIdx.x;
    const int tm = (tid >> 4) * 8;
    const int tn = (tid & 15) * 8;
    const int lm = tid >> 1;
    const int kq = (tid & 1) * 4;
    const int bkk = tid >> 5;
    const int bn4 = (tid & 31) * 4;

    ull acc2[8][4];
#pragma unroll
    for (int i = 0; i < 8; i++)
#pragma unroll
        for (int j = 0; j < 4; j++) acc2[i][j] = 0ull;

    float4 av = *reinterpret_cast<const float4*>(&A[(long)(m0 + lm) * HID + kq]);
    float4 bv = *reinterpret_cast<const float4*>(&B[(long)bkk * HID + n0 + bn4]);

    for (int k0 = 0; k0 < HID; k0 += 8) {
        As[kq + 0][lm] = av.x; As[kq + 1][lm] = av.y;
        As[kq + 2][lm] = av.z; As[kq + 3][lm] = av.w;
        *reinterpret_cast<float4*>(&Bs[bkk][bn4]) = bv;
        __syncthreads();
        if (k0 + 8 < HID) {
            av = *reinterpret_cast<const float4*>(&A[(long)(m0 + lm) * HID + k0 + 8 + kq]);
            bv = *reinterpret_cast<const float4*>(&B[(long)(k0 + 8 + bkk) * HID + n0 + bn4]);
        }
#pragma unroll
        for (int kk = 0; kk < 8; kk++) {
            float4 t0 = *reinterpret_cast<const float4*>(&As[kk][tm]);
            float4 t1 = *reinterpret_cast<const float4*>(&As[kk][tm + 4]);
            ull a2[8];
            a2[0] = pk2(t0.x, t0.x); a2[1] = pk2(t0.y, t0.y);
            a2[2] = pk2(t0.z, t0.z); a2[3] = pk2(t0.w, t0.w);
            a2[4] = pk2(t1.x, t1.x); a2[5] = pk2(t1.y, t1.y);
            a2[6] = pk2(t1.z, t1.z); a2[7] = pk2(t1.w, t1.w);
            const ull* bp = reinterpret_cast<const ull*>(&Bs[kk][tn]);
            ull b2v[4] = {bp[0], bp[1], bp[2], bp[3]};
#pragma unroll
            for (int i = 0; i < 8; i++)
#pragma unroll
                for (int j = 0; j < 4; j++) fma2(acc2[i][j], a2[i], b2v[j]);
        }
        __syncthreads();
    }
#pragma unroll
    for (int i = 0; i < 8; i++) {
        float* Cp = &C[(long)(m0 + tm + i) * HID + n0 + tn];
#pragma unroll
        for (int j = 0; j < 4; j++) {
            float lo, hi; upk2(acc2[i][j], lo, hi);
            Cp[2 * j] = lo;
            Cp[2 * j + 1] = hi;
        }
    }
}

// ---------- persistent LSTM: all 60 steps in one launch ----------
__global__ __launch_bounds__(512) void lstm_persist(
    const float* __restrict__ Wh1, const float* __restrict__ Wh2,
    const int* __restrict__ s1, const int* __restrict__ s2)
{
    const int run = blockIdx.z;
    const float* Wh = (run == 0 || run == 2) ? Wh1 : Wh2;
    const int* slen = (run == 0 || run == 3) ? s1 : s2;
    const int b0 = blockIdx.x * 64;
    const int h0 = blockIdx.y * 64;
    float* cst = g_c[run];
    float* Y = g_Ybuf[run];
    const float* XG = g_XG[run];

    const int tid = threadIdx.x;
    const int hl = tid & 31;
    const int rg = tid >> 5;   // 0..15 -> rows rg*4..+3

    __shared__ int sh_sl[64];
    __shared__ float As[2][64][20];
    __shared__ float Bs[2][16][256];

    if (tid < 64) sh_sl[tid] = slen[b0 + tid];
    __syncthreads();

    for (int t = 0; t < LSEQ; t++) {
        const float* hin = g_h[t & 1][run];
        float* hout = g_h[(t + 1) & 1][run];

        int anyAct = __syncthreads_or((tid < 64) ? (t < sh_sl[tid]) : 0);
        if (!anyAct) {
#pragma unroll
            for (int p = 0; p < 4; p++) {
                int idx = p * 512 + tid;
                int row = idx >> 5;
                int h = h0 + (idx & 31) * 2;
                int b = b0 + row;
                *reinterpret_cast<float2*>(&hout[b * HID + h]) =
                    *reinterpret_cast<const float2*>(&hin[b * HID + h]);
                *reinterpret_cast<float2*>(&Y[((long)b * LSEQ + t) * HID + h]) =
                    make_float2(0.0f, 0.0f);
            }
            grid_barrier(128u * (unsigned)(t + 1));
            continue;
        }

        auto loadAB = [&](int buf, int kb) {
            int k0 = kb * 16;
            if (tid < 256)
                cpa16(&As[buf][tid >> 2][(tid & 3) * 4],
                      &hin[(b0 + (tid >> 2)) * HID + k0 + (tid & 3) * 4], 16);
#pragma unroll
            for (int p = 0; p < 2; p++) {
                int i = p * 512 + tid;
                int kk = i >> 6;
                int cw = (i & 63) * 4;
                int g = cw >> 6;
                int wn = cw & 63;
                cpa16(&Bs[buf][kk][cw], &Wh[(long)(k0 + kk) * G4 + g * HID + h0 + wn], 16);
            }
        };

        ull acc2[4][4];
#pragma unroll
        for (int i = 0; i < 4; i++)
#pragma unroll
            for (int g = 0; g < 4; g++) acc2[i][g] = 0ull;

        const int NB = HID / 16;  // 16
        loadAB(0, 0);
        cpa_commit();

        for (int kb = 0; kb < NB; kb++) {
            int buf = kb & 1;
            if (kb + 1 < NB) { loadAB(buf ^ 1, kb + 1); cpa_commit(); cpa_wait1(); }
            else cpa_wait0();
            __syncthreads();
#pragma unroll
            for (int kk = 0; kk < 16; kk++) {
                ull a2[4];
#pragma unroll
                for (int rr = 0; rr < 4; rr++) {
                    float a = As[buf][rg * 4 + rr][kk];
                    a2[rr] = pk2(a, a);
                }
                ull b2v[4];
#pragma unroll
                for (int g = 0; g < 4; g++)
                    b2v[g] = *reinterpret_cast<const ull*>(&Bs[buf][kk][g * 64 + hl * 2]);
#pragma unroll
                for (int rr = 0; rr < 4; rr++)
#pragma unroll
                    for (int g = 0; g < 4; g++) fma2(acc2[rr][g], a2[rr], b2v[g]);
            }
            __syncthreads();
        }

        const int h = h0 + hl * 2;
#pragma unroll
        for (int rr = 0; rr < 4; rr++) {
            const int b = b0 + rg * 4 + rr;
            const bool act = t < sh_sl[rg * 4 + rr];
            const float* xg = &XG[((long)b * LSEQ + t) * G4 + h];
            float ix, iy, jx, jy, fx, fy, ox, oy;
            upk2(acc2[rr][0], ix, iy);
            upk2(acc2[rr][1], jx, jy);
            upk2(acc2[rr][2], fx, fy);
            upk2(acc2[rr][3], ox, oy);
            float2 xi = *reinterpret_cast<const float2*>(&xg[0]);
            float2 xj = *reinterpret_cast<const float2*>(&xg[HID]);
            float2 xf = *reinterpret_cast<const float2*>(&xg[2 * HID]);
            float2 xo = *reinterpret_cast<const float2*>(&xg[3 * HID]);
            ix += xi.x; iy += xi.y; jx += xj.x; jy += xj.y;
            fx += xf.x; fy += xf.y; ox += xo.x; oy += xo.y;
            float2 cold = *reinterpret_cast<const float2*>(&cst[b * HID + h]);
            float cnx = cold.x * sigm_(fx + 1.0f) + sigm_(ix) * tanh_(jx);
            float cny = cold.y * sigm_(fy + 1.0f) + sigm_(iy) * tanh_(jy);
            float hnx = tanh_(cnx) * sigm_(ox);
            float hny = tanh_(cny) * sigm_(oy);
            float2 hov, yov;
            if (act) {
                *reinterpret_cast<float2*>(&cst[b * HID + h]) = make_float2(cnx, cny);
                hov = make_float2(hnx, hny);
                yov = hov;
            } else {
                hov = *reinterpret_cast<const float2*>(&hin[b * HID + h]);
                yov = make_float2(0.0f, 0.0f);
            }
            *reinterpret_cast<float2*>(&hout[b * HID + h]) = hov;
            *reinterpret_cast<float2*>(&Y[((long)b * LSEQ + t) * HID + h]) = yov;
        }

        grid_barrier(128u * (unsigned)(t + 1));
    }
}

// ---------- persistent attention, 512 threads: halves split Wr/Wt work ----------
__global__ __launch_bounds__(512) void attn_persist(
    const float* __restrict__ Wr_a, const float* __restrict__ Wt_a,
    const float* __restrict__ w_a,
    const int* __restrict__ s1, const int* __restrict__ s2)
{
    const int br = blockIdx.y;
    const int b0 = blockIdx.x * ROWS_A;
    const float* Y  = g_Ybuf[br == 0 ? 0 : 2];
    const float* WyY = g_WyY[br];
    const float* WhY2 = g_WhY2[br];
    const int* msel  = br == 0 ? s2 : s1;
    const int* mmask = br == 0 ? s1 : s2;
    float* rsel = g_rsel[br];

    const int tid = threadIdx.x;
    const int lane = tid & 31;
    const int w = tid >> 5;        // 0..15
    const int col = tid & 255;     // column within HID
    const int half = tid >> 8;     // 0: Wr/tmp, 1: Wt/rt

    __shared__ float sh_r[ROWS_A][HID];
    __shared__ float sh_tmp[ROWS_A][HID];
    __shared__ float sh_rt[ROWS_A][HID];
    __shared__ float sh_sc[ROWS_A][64];
    __shared__ float sh_al[ROWS_A][64];
    __shared__ float sh_wa[HID];
    __shared__ int sh_sel[ROWS_A], sh_ml[ROWS_A], sh_tmax;

    if (tid < ROWS_A) { sh_sel[tid] = msel[b0 + tid]; sh_ml[tid] = mmask[b0 + tid]; }
    if (half == 0) {
        sh_wa[col] = w_a[col];
#pragma unroll
        for (int rb = 0; rb < ROWS_A; rb++) sh_r[rb][col] = 0.0f;
    }
    __syncthreads();
    if (tid == 0) {
        int m = 0;
#pragma unroll
        for (int i = 0; i < ROWS_A; i++) m = max(m, sh_sel[i]);
        sh_tmax = m;
    }
    __syncthreads();
    const int tmax = sh_tmax;

    for (int t = 0; t < tmax; t++) {
        // half 0: tmp = WhY2[:,t,:] + r @ Wr_a ; half 1: rt = r @ Wt_a
        {
            const float* Wm = half ? Wt_a : Wr_a;
            float acc[ROWS_A];
#pragma unroll
            for (int rb = 0; rb < ROWS_A; rb++) acc[rb] = 0.0f;
#pragma unroll 4
            for (int k = 0; k < HID; k++) {
                float wv = Wm[k * HID + col];
#pragma unroll
                for (int rb = 0; rb < ROWS_A; rb++)
                    acc[rb] = fmaf(sh_r[rb][k], wv, acc[rb]);
            }
            if (half == 0) {
#pragma unroll
                for (int rb = 0; rb < ROWS_A; rb++)
                    sh_tmp[rb][col] = acc[rb] + WhY2[((long)(b0 + rb) * LSEQ + t) * HID + col];
            } else {
#pragma unroll
                for (int rb = 0; rb < ROWS_A; rb++)
                    sh_rt[rb][col] = acc[rb];
            }
        }
        __syncthreads();

        // scores: 16 warps stride l by 16
        for (int rb = 0; rb < ROWS_A; rb++) {
            if (t >= sh_sel[rb]) continue;
            const int ml = sh_ml[rb];
            const float* WyYb = &WyY[((long)(b0 + rb) * LSEQ) * HID];
            for (int l = w; l < ml; l += 16) {
                float part = 0.0f;
                const float* row = &WyYb[(long)l * HID];
#pragma unroll
                for (int q = 0; q < 8; q++) {
                    int h = lane + q * 32;
                    part = fmaf(tanha(row[h] + sh_tmp[rb][h]), sh_wa[h], part);
                }
#pragma unroll
                for (int off = 16; off > 0; off >>= 1)
                    part += __shfl_xor_sync(0xFFFFFFFFu, part, off);
                if (lane == 0) sh_sc[rb][l] = part;
            }
        }
        __syncthreads();

        if (w < ROWS_A) {
            int rb = w;
            if (t < sh_sel[rb]) {
                const int ml = sh_ml[rb];
                float v0 = (lane < ml) ? sh_sc[rb][lane] : -1e30f;
                float v1 = (lane + 32 < ml) ? sh_sc[rb][lane + 32] : -1e30f;
                float m = fmaxf(v0, v1);
#pragma unroll
                for (int off = 16; off > 0; off >>= 1)
                    m = fmaxf(m, __shfl_xor_sync(0xFFFFFFFFu, m, off));
                float e0 = (lane < ml) ? __expf(v0 - m) : 0.0f;
                float e1 = (lane + 32 < ml) ? __expf(v1 - m) : 0.0f;
                float s = e0 + e1;
#pragma unroll
                for (int off = 16; off > 0; off >>= 1)
                    s += __shfl_xor_sync(0xFFFFFFFFu, s, off);
                float inv = __fdividef(1.0f, s);
                sh_al[rb][lane] = e0 * inv;
                sh_al[rb][lane + 32] = e1 * inv;
            }
        }
        __syncthreads();

        // r update: each half owns 4 rows (disjoint smem writes)
#pragma unroll
        for (int p = 0; p < 4; p++) {
            int rb = half * 4 + p;
            if (t >= sh_sel[rb]) continue;
            const int ml = sh_ml[rb];
            const float* Yb = &Y[((long)(b0 + rb) * LSEQ) * HID];
            float acc = 0.0f;
            for (int l = 0; l < ml; l++)
                acc = fmaf(sh_al[rb][l], Yb[(long)l * HID + col], acc);
            float rn = acc + tanh_(sh_rt[rb][col]);
            sh_r[rb][col] = rn;
            if (t == sh_sel[rb] - 1) rsel[(b0 + rb) * HID + col] = rn;
        }
        __syncthreads();
    }
}

// ---------- final combine ----------
__global__ __launch_bounds__(256) void final_combine(
    const float* __restrict__ Wp_a, const float* __restrict__ Wxa,
    const float* __restrict__ U, const float* __restrict__ b_out,
    float* __restrict__ out)
{
    const int b = blockIdx.x;
    const int tid = threadIdx.x;
    __shared__ float sh_a[4][HID];
    __shared__ float red0[256], red1[256];

    sh_a[0][tid] = g_rsel[0][b * HID + tid];
    sh_a[1][tid] = g_h[0][1][b * HID + tid];   // LSEQ even -> final h in buf 0
    sh_a[2][tid] = g_rsel[1][b * HID + tid];
    sh_a[3][tid] = g_h[0][3][b * HID + tid];
    __syncthreads();

    float v = 0.0f;
#pragma unroll
    for (int brn = 0; brn < 2; brn++) {
        float a = 0.0f;
#pragma unroll 4
        for (int k = 0; k < HID; k++)
            a = fmaf(sh_a[2 * brn][k], Wp_a[k * HID + tid],
                fmaf(sh_a[2 * brn + 1][k], Wxa[k * HID + tid], a));
        v += tanh_(a);
    }
    red0[tid] = v * U[tid * 2 + 0];
    red1[tid] = v * U[tid * 2 + 1];
    __syncthreads();
    for (int s = 128; s > 0; s >>= 1) {
        if (tid < s) { red0[tid] += red0[tid + s]; red1[tid] += red1[tid + s]; }
        __syncthreads();
    }
    if (tid == 0) {
        out[b * 2 + 0] = red0[0] + b_out[0];
        out[b * 2 + 1] = red1[0] + b_out[1];
    }
}

extern "C" void kernel_launch(void* const* d_in, const int* in_sizes, int n_in,
                              void* d_out, int out_size) {
    const float* E    = (const float*)d_in[0];
    const float* Wx1  = (const float*)d_in[1];
    const float* Wh1  = (const float*)d_in[2];
    const float* b1   = (const float*)d_in[3];
    const float* Wx2  = (const float*)d_in[4];
    const float* Wh2  = (const float*)d_in[5];
    const float* b2   = (const float*)d_in[6];
    const float* W_y  = (const float*)d_in[7];
    const float* Wh_a = (const float*)d_in[8];
    const float* Wr_a = (const float*)d_in[9];
    const float* w_a  = (const float*)d_in[10];
    const float* Wt_a = (const float*)d_in[11];
    const float* Wp_a = (const float*)d_in[12];
    const float* Wxa  = (const float*)d_in[13];
    const float* U    = (const float*)d_in[14];
    const float* b_out= (const float*)d_in[15];
    const int* input1 = (const int*)d_in[16];
    const int* input2 = (const int*)d_in[17];
    const int* s1     = (const int*)d_in[18];
    const int* s2     = (const int*)d_in[19];
    float* out = (float*)d_out;

    init_kernel<<<256, 256>>>();
    xg_gemm<<<dim3(240, 16, 2), 256>>>(E, Wx1, b1, Wx2, b2, input1, input2);
    lstm_persist<<<dim3(8, 4, 4), 512>>>(Wh1, Wh2, s1, s2);
    bgemm<<<dim3(240, 2, 4), 256>>>(W_y, Wh_a);
    attn_persist<<<dim3(BSZ / ROWS_A, 2), 512>>>(Wr_a, Wt_a, w_a, s1, s2);
    final_combine<<<BSZ, 256>>>(Wp_a, Wxa, U, b_out, out);
}

// round 17
// speedup vs baseline: 1.2359x; 1.0081x over previous
#include <cuda_runtime.h>
#include <cuda_bf16.h>

#define BSZ 512
#define LSEQ 60
#define DIM 300
#define HID 256
#define G4 1024
#define ROWS_A 8

typedef unsigned long long ull;

// run map: 0=lstm1(x1,s1) 1=lstm2(x2,s2) 2=lstm1(x2,s2) 3=lstm2(x1,s1)
__device__ float g_XG[4][(size_t)BSZ * LSEQ * G4];
__device__ float g_Ybuf[4][(size_t)BSZ * LSEQ * HID];
__device__ float g_h[2][4][BSZ * HID];
__device__ float g_c[4][BSZ * HID];
__device__ float g_WyY[2][(size_t)BSZ * LSEQ * HID];
__device__ float g_WhY2[2][(size_t)BSZ * LSEQ * HID];
__device__ float g_rsel[2][BSZ * HID];
__device__ unsigned g_barL;

__device__ __forceinline__ float tanh_(float x) {
    x = fminf(15.0f, fmaxf(-15.0f, x));
    float e = __expf(2.0f * x);
    return __fdividef(e - 1.0f, e + 1.0f);
}
__device__ __forceinline__ float sigm_(float x) {
    x = fminf(30.0f, fmaxf(-30.0f, x));
    return __fdividef(1.0f, 1.0f + __expf(-x));
}
__device__ __forceinline__ float tanha(float x) {   // HW tanh MUFU op
    float y; asm("tanh.approx.f32 %0, %1;" : "=f"(y) : "f"(x)); return y;
}

// ---- packed f32x2 helpers ----
__device__ __forceinline__ ull pk2(float x, float y) {
    ull r; asm("mov.b64 %0, {%1, %2};" : "=l"(r) : "f"(x), "f"(y)); return r;
}
__device__ __forceinline__ void fma2(ull& d, ull a, ull b) {
    asm("fma.rn.f32x2 %0, %1, %2, %0;" : "+l"(d) : "l"(a), "l"(b));
}
__device__ __forceinline__ void upk2(ull v, float& lo, float& hi) {
    asm("mov.b64 {%0, %1}, %2;" : "=f"(lo), "=f"(hi) : "l"(v));
}

// ---- cp.async helpers ----
__device__ __forceinline__ void cpa16(void* dst, const void* src, int bytes) {
    unsigned d = (unsigned)__cvta_generic_to_shared(dst);
    asm volatile("cp.async.cg.shared.global [%0], [%1], 16, %2;" :: "r"(d), "l"(src), "r"(bytes));
}
__device__ __forceinline__ void cpa_commit() { asm volatile("cp.async.commit_group;"); }
__device__ __forceinline__ void cpa_wait1() { asm volatile("cp.async.wait_group 1;"); }
__device__ __forceinline__ void cpa_wait0() { asm volatile("cp.async.wait_group 0;"); }

// ---- software grid barrier (all CTAs resident by construction) ----
__device__ __forceinline__ void grid_barrier(unsigned target) {
    __syncthreads();
    if (threadIdx.x == 0) {
        __threadfence();
        atomicAdd(&g_barL, 1u);
        while (*(volatile unsigned*)&g_barL < target) {}
        __threadfence();
    }
    __syncthreads();
}

__global__ void init_kernel() {
    int idx = blockIdx.x * blockDim.x + threadIdx.x;
    int stride = gridDim.x * blockDim.x;
    const int n = BSZ * HID;
    float* ph = &g_h[0][0][0];
    float* pc = &g_c[0][0];
    float* ps = &g_rsel[0][0];
    for (int i = idx; i < 8 * n; i += stride) ph[i] = 0.0f;
    for (int i = idx; i < 4 * n; i += stride) pc[i] = 0.0f;
    for (int i = idx; i < 2 * n; i += stride) ps[i] = 0.0f;
    if (idx == 0) g_barL = 0u;
}

// ---------- gather + input projection: XG[run] = E[tok] @ Wx + b ----------
__global__ __launch_bounds__(256, 2) void xg_gemm(
    const float* __restrict__ E,
    const float* __restrict__ Wx1, const float* __restrict__ b1,
    const float* __restrict__ Wx2, const float* __restrict__ b2,
    const int* __restrict__ in1, const int* __restrict__ in2)
{
    const int src = blockIdx.z;
    const int* tok = src == 0 ? in1 : in2;
    const int m0 = blockIdx.x * 128;
    const int n0g = blockIdx.y * 128;
    const bool isW2 = n0g >= G4;
    const float* W = isW2 ? Wx2 : Wx1;
    const float* bias = isW2 ? b2 : b1;
    const int n0 = isW2 ? (n0g - G4) : n0g;
    const int run = isW2 ? (src == 0 ? 3 : 1) : (src == 0 ? 0 : 2);
    float* C = g_XG[run];

    __shared__ float As[8][128];
    __shared__ float Bs[8][128];

    const int tid = threadIdx.x;
    const int tm = (tid >> 4) * 8;
    const int cthr = tid & 15;
    const int lm = tid >> 1;
    const int kq = (tid & 1) * 4;
    const int bkk = tid >> 5;
    const int bn4 = (tid & 31) * 4;
    const long aBase = (long)tok[m0 + lm] * DIM;

    const int NB = (DIM + 7) / 8;        // 38

    ull acc2[8][4];
#pragma unroll
    for (int i = 0; i < 8; i++)
#pragma unroll
        for (int j = 0; j < 4; j++) acc2[i][j] = 0ull;

    float4 av, bv;
    av = *reinterpret_cast<const float4*>(&E[aBase + kq]);
    bv = *reinterpret_cast<const float4*>(&W[(long)bkk * G4 + n0 + bn4]);

    for (int kb = 0; kb < NB; kb++) {
        As[kq + 0][lm] = av.x; As[kq + 1][lm] = av.y;
        As[kq + 2][lm] = av.z; As[kq + 3][lm] = av.w;
        *reinterpret_cast<float4*>(&Bs[bkk][bn4]) = bv;
        __syncthreads();
        if (kb + 1 < NB) {
            int kA = (kb + 1) * 8 + kq;
            av = (kA < DIM) ? *reinterpret_cast<const float4*>(&E[aBase + kA])
                            : make_float4(0.f, 0.f, 0.f, 0.f);
            int kB = (kb + 1) * 8 + bkk;
            bv = (kB < DIM) ? *reinterpret_cast<const float4*>(&W[(long)kB * G4 + n0 + bn4])
                            : make_float4(0.f, 0.f, 0.f, 0.f);
        }
#pragma unroll
        for (int kk = 0; kk < 8; kk++) {
            float4 t0 = *reinterpret_cast<const float4*>(&As[kk][tm]);
            float4 t1 = *reinterpret_cast<const float4*>(&As[kk][tm + 4]);
            ull a2[8];
            a2[0] = pk2(t0.x, t0.x); a2[1] = pk2(t0.y, t0.y);
            a2[2] = pk2(t0.z, t0.z); a2[3] = pk2(t0.w, t0.w);
            a2[4] = pk2(t1.x, t1.x); a2[5] = pk2(t1.y, t1.y);
            a2[6] = pk2(t1.z, t1.z); a2[7] = pk2(t1.w, t1.w);
            ull b2v[4];
#pragma unroll
            for (int j = 0; j < 4; j++)
                b2v[j] = *reinterpret_cast<const ull*>(&Bs[kk][2 * cthr + 32 * j]);
#pragma unroll
            for (int i = 0; i < 8; i++)
#pragma unroll
                for (int j = 0; j < 4; j++) fma2(acc2[i][j], a2[i], b2v[j]);
        }
        __syncthreads();
    }

#pragma unroll
    for (int i = 0; i < 8; i++) {
        const long rowOff = (long)(m0 + tm + i) * G4 + n0;
#pragma unroll
        for (int j = 0; j < 4; j++) {
            int col = 2 * cthr + 32 * j;
            float lo, hi; upk2(acc2[i][j], lo, hi);
            float2 v = make_float2(lo + bias[n0 + col], hi + bias[n0 + col + 1]);
            *reinterpret_cast<float2*>(&C[rowOff + col]) = v;
        }
    }
}

// ---------- batched [30720,256]x[256,128] products, register-prefetch pipelined ----------
__global__ __launch_bounds__(256, 2) void bgemm(
    const float* __restrict__ W_y, const float* __restrict__ Wh_a)
{
    const int z = blockIdx.z;
    const float* A = g_Ybuf[z == 0 ? 0 : z == 1 ? 2 : z == 2 ? 1 : 3];
    const float* B = (z < 2) ? W_y : Wh_a;
    float* C = (z < 2) ? g_WyY[z] : g_WhY2[z - 2];
    const int m0 = blockIdx.x * 128;
    const int n0 = blockIdx.y * 128;

    __shared__ float As[8][128];
    __shared__ float Bs[8][128];

    const int tid = threadIdx.x;
    const int tm = (tid >> 4) * 8;
    const int tn = (tid & 15) * 8;
    const int lm = tid >> 1;
    const int kq = (tid & 1) * 4;
    const int bkk = tid >> 5;
    const int bn4 = (tid & 31) * 4;

    ull acc2[8][4];
#pragma unroll
    for (int i = 0; i < 8; i++)
#pragma unroll
        for (int j = 0; j < 4; j++) acc2[i][j] = 0ull;

    float4 av = *reinterpret_cast<const float4*>(&A[(long)(m0 + lm) * HID + kq]);
    float4 bv = *reinterpret_cast<const float4*>(&B[(long)bkk * HID + n0 + bn4]);

    for (int k0 = 0; k0 < HID; k0 += 8) {
        As[kq + 0][lm] = av.x; As[kq + 1][lm] = av.y;
        As[kq + 2][lm] = av.z; As[kq + 3][lm] = av.w;
        *reinterpret_cast<float4*>(&Bs[bkk][bn4]) = bv;
        __syncthreads();
        if (k0 + 8 < HID) {
            av = *reinterpret_cast<const float4*>(&A[(long)(m0 + lm) * HID + k0 + 8 + kq]);
            bv = *reinterpret_cast<const float4*>(&B[(long)(k0 + 8 + bkk) * HID + n0 + bn4]);
        }
#pragma unroll
        for (int kk = 0; kk < 8; kk++) {
            float4 t0 = *reinterpret_cast<const float4*>(&As[kk][tm]);
            float4 t1 = *reinterpret_cast<const float4*>(&As[kk][tm + 4]);
            ull a2[8];
            a2[0] = pk2(t0.x, t0.x); a2[1] = pk2(t0.y, t0.y);
            a2[2] = pk2(t0.z, t0.z); a2[3] = pk2(t0.w, t0.w);
            a2[4] = pk2(t1.x, t1.x); a2[5] = pk2(t1.y, t1.y);
            a2[6] = pk2(t1.z, t1.z); a2[7] = pk2(t1.w, t1.w);
            const ull* bp = reinterpret_cast<const ull*>(&Bs[kk][tn]);
            ull b2v[4] = {bp[0], bp[1], bp[2], bp[3]};
#pragma unroll
            for (int i = 0; i < 8; i++)
#pragma unroll
                for (int j = 0; j < 4; j++) fma2(acc2[i][j], a2[i], b2v[j]);
        }
        __syncthreads();
    }
#pragma unroll
    for (int i = 0; i < 8; i++) {
        float* Cp = &C[(long)(m0 + tm + i) * HID + n0 + tn];
#pragma unroll
        for (int j = 0; j < 4; j++) {
            float lo, hi; upk2(acc2[i][j], lo, hi);
            Cp[2 * j] = lo;
            Cp[2 * j + 1] = hi;
        }
    }
}

// ---------- persistent LSTM: all 60 steps in one launch ----------
__global__ __launch_bounds__(512) void lstm_persist(
    const float* __restrict__ Wh1, const float* __restrict__ Wh2,
    const int* __restrict__ s1, const int* __restrict__ s2)
{
    const int run = blockIdx.z;
    const float* Wh = (run == 0 || run == 2) ? Wh1 : Wh2;
    const int* slen = (run == 0 || run == 3) ? s1 : s2;
    const int b0 = blockIdx.x * 64;
    const int h0 = blockIdx.y * 64;
    float* cst = g_c[run];
    float* Y = g_Ybuf[run];
    const float* XG = g_XG[run];

    const int tid = threadIdx.x;
    const int hl = tid & 31;
    const int rg = tid >> 5;   // 0..15 -> rows rg*4..+3

    __shared__ int sh_sl[64];
    __shared__ float As[2][64][20];
    __shared__ float Bs[2][16][256];

    if (tid < 64) sh_sl[tid] = slen[b0 + tid];
    __syncthreads();

    for (int t = 0; t < LSEQ; t++) {
        const float* hin = g_h[t & 1][run];
        float* hout = g_h[(t + 1) & 1][run];

        int anyAct = __syncthreads_or((tid < 64) ? (t < sh_sl[tid]) : 0);
        if (!anyAct) {
#pragma unroll
            for (int p = 0; p < 4; p++) {
                int idx = p * 512 + tid;
                int row = idx >> 5;
                int h = h0 + (idx & 31) * 2;
                int b = b0 + row;
                *reinterpret_cast<float2*>(&hout[b * HID + h]) =
                    *reinterpret_cast<const float2*>(&hin[b * HID + h]);
                *reinterpret_cast<float2*>(&Y[((long)b * LSEQ + t) * HID + h]) =
                    make_float2(0.0f, 0.0f);
            }
            grid_barrier(128u * (unsigned)(t + 1));
            continue;
        }

        auto loadAB = [&](int buf, int kb) {
            int k0 = kb * 16;
            if (tid < 256)
                cpa16(&As[buf][tid >> 2][(tid & 3) * 4],
                      &hin[(b0 + (tid >> 2)) * HID + k0 + (tid & 3) * 4], 16);
#pragma unroll
            for (int p = 0; p < 2; p++) {
                int i = p * 512 + tid;
                int kk = i >> 6;
                int cw = (i & 63) * 4;
                int g = cw >> 6;
                int wn = cw & 63;
                cpa16(&Bs[buf][kk][cw], &Wh[(long)(k0 + kk) * G4 + g * HID + h0 + wn], 16);
            }
        };

        ull acc2[4][4];
#pragma unroll
        for (int i = 0; i < 4; i++)
#pragma unroll
            for (int g = 0; g < 4; g++) acc2[i][g] = 0ull;

        const int NB = HID / 16;  // 16
        loadAB(0, 0);
        cpa_commit();

        for (int kb = 0; kb < NB; kb++) {
            int buf = kb & 1;
            if (kb + 1 < NB) { loadAB(buf ^ 1, kb + 1); cpa_commit(); cpa_wait1(); }
            else cpa_wait0();
            __syncthreads();
#pragma unroll
            for (int kk = 0; kk < 16; kk++) {
                ull a2[4];
#pragma unroll
                for (int rr = 0; rr < 4; rr++) {
                    float a = As[buf][rg * 4 + rr][kk];
                    a2[rr] = pk2(a, a);
                }
                ull b2v[4];
#pragma unroll
                for (int g = 0; g < 4; g++)
                    b2v[g] = *reinterpret_cast<const ull*>(&Bs[buf][kk][g * 64 + hl * 2]);
#pragma unroll
                for (int rr = 0; rr < 4; rr++)
#pragma unroll
                    for (int g = 0; g < 4; g++) fma2(acc2[rr][g], a2[rr], b2v[g]);
            }
            __syncthreads();
        }

        const int h = h0 + hl * 2;
#pragma unroll
        for (int rr = 0; rr < 4; rr++) {
            const int b = b0 + rg * 4 + rr;
            const bool act = t < sh_sl[rg * 4 + rr];
            const float* xg = &XG[((long)b * LSEQ + t) * G4 + h];
            float ix, iy, jx, jy, fx, fy, ox, oy;
            upk2(acc2[rr][0], ix, iy);
            upk2(acc2[rr][1], jx, jy);
            upk2(acc2[rr][2], fx, fy);
            upk2(acc2[rr][3], ox, oy);
            float2 xi = *reinterpret_cast<const float2*>(&xg[0]);
            float2 xj = *reinterpret_cast<const float2*>(&xg[HID]);
            float2 xf = *reinterpret_cast<const float2*>(&xg[2 * HID]);
            float2 xo = *reinterpret_cast<const float2*>(&xg[3 * HID]);
            ix += xi.x; iy += xi.y; jx += xj.x; jy += xj.y;
            fx += xf.x; fy += xf.y; ox += xo.x; oy += xo.y;
            float2 cold = *reinterpret_cast<const float2*>(&cst[b * HID + h]);
            float cnx = cold.x * sigm_(fx + 1.0f) + sigm_(ix) * tanh_(jx);
            float cny = cold.y * sigm_(fy + 1.0f) + sigm_(iy) * tanh_(jy);
            float hnx = tanh_(cnx) * sigm_(ox);
            float hny = tanh_(cny) * sigm_(oy);
            float2 hov, yov;
            if (act) {
                *reinterpret_cast<float2*>(&cst[b * HID + h]) = make_float2(cnx, cny);
                hov = make_float2(hnx, hny);
                yov = hov;
            } else {
                hov = *reinterpret_cast<const float2*>(&hin[b * HID + h]);
                yov = make_float2(0.0f, 0.0f);
            }
            *reinterpret_cast<float2*>(&hout[b * HID + h]) = hov;
            *reinterpret_cast<float2*>(&Y[((long)b * LSEQ + t) * HID + h]) = yov;
        }

        grid_barrier(128u * (unsigned)(t + 1));
    }
}

// ---------- persistent attention, 512 threads: halves split Wr/Wt work ----------
__global__ __launch_bounds__(512) void attn_persist(
    const float* __restrict__ Wr_a, const float* __restrict__ Wt_a,
    const float* __restrict__ w_a,
    const int* __restrict__ s1, const int* __restrict__ s2)
{
    const int br = blockIdx.y;
    const int b0 = blockIdx.x * ROWS_A;
    const float* Y  = g_Ybuf[br == 0 ? 0 : 2];
    const float* WyY = g_WyY[br];
    const float* WhY2 = g_WhY2[br];
    const int* msel  = br == 0 ? s2 : s1;
    const int* mmask = br == 0 ? s1 : s2;
    float* rsel = g_rsel[br];

    const int tid = threadIdx.x;
    const int lane = tid & 31;
    const int w = tid >> 5;        // 0..15
    const int col = tid & 255;     // column within HID
    const int half = tid >> 8;     // 0: Wr/tmp, 1: Wt/rt

    __shared__ float sh_r[ROWS_A][HID];
    __shared__ float sh_tmp[ROWS_A][HID];
    __shared__ float sh_rt[ROWS_A][HID];
    __shared__ float sh_sc[ROWS_A][64];
    __shared__ float sh_al[ROWS_A][64];
    __shared__ float sh_wa[HID];
    __shared__ int sh_sel[ROWS_A], sh_ml[ROWS_A], sh_tmax;

    if (tid < ROWS_A) { sh_sel[tid] = msel[b0 + tid]; sh_ml[tid] = mmask[b0 + tid]; }
    if (half == 0) {
        sh_wa[col] = w_a[col];
#pragma unroll
        for (int rb = 0; rb < ROWS_A; rb++) sh_r[rb][col] = 0.0f;
    }
    __syncthreads();
    if (tid == 0) {
        int m = 0;
#pragma unroll
        for (int i = 0; i < ROWS_A; i++) m = max(m, sh_sel[i]);
        sh_tmax = m;
    }
    __syncthreads();
    const int tmax = sh_tmax;

    for (int t = 0; t < tmax; t++) {
        // half 0: tmp = WhY2[:,t,:] + r @ Wr_a ; half 1: rt = r @ Wt_a
        // k stepped by 4: sh_r read as float4 broadcast (2 LDS.128 per 4k per row-set)
        {
            const float* Wm = half ? Wt_a : Wr_a;
            float acc[ROWS_A];
#pragma unroll
            for (int rb = 0; rb < ROWS_A; rb++) acc[rb] = 0.0f;
#pragma unroll 2
            for (int k0 = 0; k0 < HID; k0 += 4) {
                float w0 = Wm[(k0 + 0) * HID + col];
                float w1 = Wm[(k0 + 1) * HID + col];
                float w2 = Wm[(k0 + 2) * HID + col];
                float w3 = Wm[(k0 + 3) * HID + col];
#pragma unroll
                for (int rb = 0; rb < ROWS_A; rb++) {
                    float4 rv = *reinterpret_cast<const float4*>(&sh_r[rb][k0]);
                    acc[rb] = fmaf(rv.x, w0,
                              fmaf(rv.y, w1,
                              fmaf(rv.z, w2,
                              fmaf(rv.w, w3, acc[rb]))));
                }
            }
            if (half == 0) {
#pragma unroll
                for (int rb = 0; rb < ROWS_A; rb++)
                    sh_tmp[rb][col] = acc[rb] + WhY2[((long)(b0 + rb) * LSEQ + t) * HID + col];
            } else {
#pragma unroll
                for (int rb = 0; rb < ROWS_A; rb++)
                    sh_rt[rb][col] = acc[rb];
            }
        }
        __syncthreads();

        // scores: 16 warps stride l by 16
        for (int rb = 0; rb < ROWS_A; rb++) {
            if (t >= sh_sel[rb]) continue;
            const int ml = sh_ml[rb];
            const float* WyYb = &WyY[((long)(b0 + rb) * LSEQ) * HID];
            for (int l = w; l < ml; l += 16) {
                float part = 0.0f;
                const float* row = &WyYb[(long)l * HID];
#pragma unroll
                for (int q = 0; q < 8; q++) {
                    int h = lane + q * 32;
                    part = fmaf(tanha(row[h] + sh_tmp[rb][h]), sh_wa[h], part);
                }
#pragma unroll
                for (int off = 16; off > 0; off >>= 1)
                    part += __shfl_xor_sync(0xFFFFFFFFu, part, off);
                if (lane == 0) sh_sc[rb][l] = part;
            }
        }
        __syncthreads();

        if (w < ROWS_A) {
            int rb = w;
            if (t < sh_sel[rb]) {
                const int ml = sh_ml[rb];
                float v0 = (lane < ml) ? sh_sc[rb][lane] : -1e30f;
                float v1 = (lane + 32 < ml) ? sh_sc[rb][lane + 32] : -1e30f;
                float m = fmaxf(v0, v1);
#pragma unroll
                for (int off = 16; off > 0; off >>= 1)
                    m = fmaxf(m, __shfl_xor_sync(0xFFFFFFFFu, m, off));
                float e0 = (lane < ml) ? __expf(v0 - m) : 0.0f;
                float e1 = (lane + 32 < ml) ? __expf(v1 - m) : 0.0f;
                float s = e0 + e1;
#pragma unroll
                for (int off = 16; off > 0; off >>= 1)
                    s += __shfl_xor_sync(0xFFFFFFFFu, s, off);
                float inv = __fdividef(1.0f, s);
                sh_al[rb][lane] = e0 * inv;
                sh_al[rb][lane + 32] = e1 * inv;
            }
        }
        __syncthreads();

        // r update: each half owns 4 rows; dual accumulator chains
#pragma unroll
        for (int p = 0; p < 4; p++) {
            int rb = half * 4 + p;
            if (t >= sh_sel[rb]) continue;
            const int ml = sh_ml[rb];
            const float* Yb = &Y[((long)(b0 + rb) * LSEQ) * HID];
            float acc0 = 0.0f, acc1 = 0.0f;
            int l = 0;
            for (; l + 1 < ml; l += 2) {
                acc0 = fmaf(sh_al[rb][l], Yb[(long)l * HID + col], acc0);
                acc1 = fmaf(sh_al[rb][l + 1], Yb[(long)(l + 1) * HID + col], acc1);
            }
            if (l < ml) acc0 = fmaf(sh_al[rb][l], Yb[(long)l * HID + col], acc0);
            float rn = acc0 + acc1 + tanh_(sh_rt[rb][col]);
            sh_r[rb][col] = rn;
            if (t == sh_sel[rb] - 1) rsel[(b0 + rb) * HID + col] = rn;
        }
        __syncthreads();
    }
}

// ---------- final combine ----------
__global__ __launch_bounds__(256) void final_combine(
    const float* __restrict__ Wp_a, const float* __restrict__ Wxa,
    const float* __restrict__ U, const float* __restrict__ b_out,
    float* __restrict__ out)
{
    const int b = blockIdx.x;
    const int tid = threadIdx.x;
    __shared__ float sh_a[4][HID];
    __shared__ float red0[256], red1[256];

    sh_a[0][tid] = g_rsel[0][b * HID + tid];
    sh_a[1][tid] = g_h[0][1][b * HID + tid];   // LSEQ even -> final h in buf 0
    sh_a[2][tid] = g_rsel[1][b * HID + tid];
    sh_a[3][tid] = g_h[0][3][b * HID + tid];
    __syncthreads();

    float v = 0.0f;
#pragma unroll
    for (int brn = 0; brn < 2; brn++) {
        float a = 0.0f;
#pragma unroll 4
        for (int k = 0; k < HID; k++)
            a = fmaf(sh_a[2 * brn][k], Wp_a[k * HID + tid],
                fmaf(sh_a[2 * brn + 1][k], Wxa[k * HID + tid], a));
        v += tanh_(a);
    }
    red0[tid] = v * U[tid * 2 + 0];
    red1[tid] = v * U[tid * 2 + 1];
    __syncthreads();
    for (int s = 128; s > 0; s >>= 1) {
        if (tid < s) { red0[tid] += red0[tid + s]; red1[tid] += red1[tid + s]; }
        __syncthreads();
    }
    if (tid == 0) {
        out[b * 2 + 0] = red0[0] + b_out[0];
        out[b * 2 + 1] = red1[0] + b_out[1];
    }
}

extern "C" void kernel_launch(void* const* d_in, const int* in_sizes, int n_in,
                              void* d_out, int out_size) {
    const float* E    = (const float*)d_in[0];
    const float* Wx1  = (const float*)d_in[1];
    const float* Wh1  = (const float*)d_in[2];
    const float* b1   = (const float*)d_in[3];
    const float* Wx2  = (const float*)d_in[4];
    const float* Wh2  = (const float*)d_in[5];
    const float* b2   = (const float*)d_in[6];
    const float* W_y  = (const float*)d_in[7];
    const float* Wh_a = (const float*)d_in[8];
    const float* Wr_a = (const float*)d_in[9];
    const float* w_a  = (const float*)d_in[10];
    const float* Wt_a = (const float*)d_in[11];
    const float* Wp_a = (const float*)d_in[12];
    const float* Wxa  = (const float*)d_in[13];
    const float* U    = (const float*)d_in[14];
    const float* b_out= (const float*)d_in[15];
    const int* input1 = (const int*)d_in[16];
    const int* input2 = (const int*)d_in[17];
    const int* s1     = (const int*)d_in[18];
    const int* s2     = (const int*)d_in[19];
    float* out = (float*)d_out;

    init_kernel<<<256, 256>>>();
    xg_gemm<<<dim3(240, 16, 2), 256>>>(E, Wx1, b1, Wx2, b2, input1, input2);
    lstm_persist<<<dim3(8, 4, 4), 512>>>(Wh1, Wh2, s1, s2);
    bgemm<<<dim3(240, 2, 4), 256>>>(W_y, Wh_a);
    attn_persist<<<dim3(BSZ / ROWS_A, 2), 512>>>(Wr_a, Wt_a, w_a, s1, s2);
    final_combine<<<BSZ, 256>>>(Wp_a, Wxa, U, b_out, out);
}